// round 4
// baseline (speedup 1.0000x reference)
#include <cuda_runtime.h>
#include <math.h>
#include <float.h>
#include <stdint.h>

#define VOCAB 30000
#define EMB   300
#define FEAT  2048
#define BATCH 256
#define NQ    32
#define NW    12
#define NK    64

#define KPAD  304           // EMB padded to /16 floats for float4 K-loops
#define NPADB 320           // B-operand rows padded for projection GEMM

// ---------------- scratch (static device globals; no runtime alloc) ----------
__device__ float g_P[(size_t)BATCH * NQ * KPAD];   // pooled p_emb, K-padded, ~10 MB
__device__ float g_Wc[NPADB * KPAD];               // Wp + 1e-5*Wm, padded/zeroed
__device__ float g_bc[NPADB];                      // bp + 1e-5*bm, padded/zeroed

// ---------------- kernel 0: combine projection weights -----------------------
__global__ void combine_kernel(const float* __restrict__ Wp, const float* __restrict__ bp,
                               const float* __restrict__ Wm, const float* __restrict__ bm)
{
    int idx = blockIdx.x * blockDim.x + threadIdx.x;
    if (idx < NPADB * KPAD) {
        int n = idx / KPAD, k = idx % KPAD;
        float v = 0.f;
        if (n < EMB && k < EMB) v = Wp[n * EMB + k] + 1e-5f * Wm[n * EMB + k];
        g_Wc[idx] = v;
    }
    if (idx < NPADB) {
        g_bc[idx] = (idx < EMB) ? (bp[idx] + 1e-5f * bm[idx]) : 0.f;
    }
}

// ---------------- kernel 1 & 3: NT SGEMM  C = A*B^T + bias (+ wv[label] gather)
// A: [M,K] row-major (lda), B: [Nreal?,K] row-major (ldb), C: [M,EMB] stride EMB
// M multiple of 128, K multiple of 16. B rows guarded vs Nreal.
#define BM 128
#define BN 64
#define BKK 16
#define ASTR 132
#define BSTR 68

__global__ __launch_bounds__(256)
void gemm_nt_kernel(const float* __restrict__ A, int lda,
                    const float* __restrict__ Bmat, int ldb, int Nreal,
                    const float* __restrict__ bias,
                    const float* __restrict__ wv, const int* __restrict__ label,
                    float* __restrict__ C, int K)
{
    __shared__ __align__(16) float As[BKK * ASTR];
    __shared__ __align__(16) float Bs[BKK * BSTR];

    const int t  = threadIdx.x;
    const int tx = t & 15;          // 0..15 -> 4 cols each
    const int ty = t >> 4;          // 0..15 -> 8 rows each
    const int m0 = blockIdx.x * BM;
    const int n0 = blockIdx.y * BN;

    float acc[8][4];
#pragma unroll
    for (int i = 0; i < 8; i++)
#pragma unroll
        for (int j = 0; j < 4; j++) acc[i][j] = 0.f;

    for (int k0 = 0; k0 < K; k0 += BKK) {
        // A tile: 128x16 = 512 float4, transposed store into As[k][m]
#pragma unroll
        for (int i = 0; i < 2; i++) {
            int idx = t + i * 256;
            int row = idx >> 2;
            int kc  = (idx & 3) * 4;
            float4 v = *(const float4*)&A[(size_t)(m0 + row) * lda + k0 + kc];
            As[(kc + 0) * ASTR + row] = v.x;
            As[(kc + 1) * ASTR + row] = v.y;
            As[(kc + 2) * ASTR + row] = v.z;
            As[(kc + 3) * ASTR + row] = v.w;
        }
        // B tile: 64x16 = 256 float4 (row-guarded), transposed into Bs[k][n]
        {
            int row = t >> 2;
            int kc  = (t & 3) * 4;
            int n   = n0 + row;
            float4 v = make_float4(0.f, 0.f, 0.f, 0.f);
            if (n < Nreal) v = *(const float4*)&Bmat[(size_t)n * ldb + k0 + kc];
            Bs[(kc + 0) * BSTR + row] = v.x;
            Bs[(kc + 1) * BSTR + row] = v.y;
            Bs[(kc + 2) * BSTR + row] = v.z;
            Bs[(kc + 3) * BSTR + row] = v.w;
        }
        __syncthreads();

#pragma unroll
        for (int kk = 0; kk < BKK; kk++) {
            float4 a0 = *(const float4*)&As[kk * ASTR + ty * 8];
            float4 a1 = *(const float4*)&As[kk * ASTR + ty * 8 + 4];
            float4 b0 = *(const float4*)&Bs[kk * BSTR + tx * 4];
            float a[8] = {a0.x, a0.y, a0.z, a0.w, a1.x, a1.y, a1.z, a1.w};
            float b[4] = {b0.x, b0.y, b0.z, b0.w};
#pragma unroll
            for (int i = 0; i < 8; i++)
#pragma unroll
                for (int j = 0; j < 4; j++) acc[i][j] += a[i] * b[j];
        }
        __syncthreads();
    }

    // epilogue: bias (+ optional wv[label[m]] gather), store to C stride EMB
#pragma unroll
    for (int i = 0; i < 8; i++) {
        int m = m0 + ty * 8 + i;
        int lab = label ? label[m] : 0;
#pragma unroll
        for (int j = 0; j < 4; j++) {
            int n = n0 + tx * 4 + j;
            if (n < EMB) {
                float v = acc[i][j] + bias[n];
                if (label) v += wv[(size_t)lab * EMB + n];
                C[(size_t)m * EMB + n] = v;
            }
        }
    }
}

// ---------------- kernel 2: attention + word-softmax pooling ------------------
// One block per batch. 256 threads = 4 groups of 64 (thread <-> object k),
// each group handles one query; 12 word-accumulators per thread (register reuse).
#define KSTR 308            // smem row stride: 308 % 32 == 20 == 4*odd -> LDS.128 at floor

__global__ __launch_bounds__(256)
void attn_kernel(const float* __restrict__ wv, const int* __restrict__ query,
                 const float* __restrict__ kemb)
{
    extern __shared__ __align__(16) float sm[];
    float* sK   = sm;                       // 64 * 308
    float* sQ   = sK + NK * KSTR;           // 48 * 308
    float* sAtt = sQ + 48 * KSTR;           // 48 * 64
    float* sRed = sAtt + 48 * 64;           // 48   (1/sum_exp per (g,w))
    float* sW   = sRed + 48;                // 48   (word weights)
    int*   sQi  = (int*)(sW + 48);          // 48   (word token ids)

    const int b    = blockIdx.x;
    const int t    = threadIdx.x;
    const int g    = t >> 6;                // query group 0..3
    const int lg   = t & 63;                // object index k
    const int lane = t & 31;
    const int wid  = t >> 5;

    // load k_emb[b] into smem (scalar coalesced; rows are 1200B, not 16B aligned)
    const float* kb = kemb + (size_t)b * NK * EMB;
    for (int idx = t; idx < NK * EMB; idx += 256)
        sK[(idx / EMB) * KSTR + (idx % EMB)] = kb[idx];

    const float scale = 0.0577350269189626f;   // 1/sqrt(300)

    for (int qb = 0; qb < NQ; qb += 4) {
        __syncthreads();                      // sK visible / sQ reuse safe
        if (t < 48) {
            int q = qb + (t / NW);
            sQi[t] = query[((size_t)b * NQ + q) * NW + (t % NW)];
        }
        __syncthreads();
        // gather q_emb rows (48 x 300)
        for (int idx = t; idx < 48 * EMB; idx += 256) {
            int row = idx / EMB, col = idx % EMB;
            sQ[row * KSTR + col] = wv[(size_t)sQi[row] * EMB + col];
        }
        __syncthreads();

        // att[w] for this thread's (g, k): dot over d with 12x k-value reuse
        float acc[NW];
#pragma unroll
        for (int w = 0; w < NW; w++) acc[w] = 0.f;
        const float* kr = &sK[lg * KSTR];
        const float* qr = &sQ[g * NW * KSTR];
        for (int d = 0; d < EMB; d += 4) {
            float4 kv = *(const float4*)&kr[d];
#pragma unroll
            for (int w = 0; w < NW; w++) {
                float4 qv = *(const float4*)&qr[w * KSTR + d];
                acc[w] += kv.x * qv.x + kv.y * qv.y + kv.z * qv.z + kv.w * qv.w;
            }
        }
#pragma unroll
        for (int w = 0; w < NW; w++) sAtt[(g * NW + w) * NK + lg] = acc[w] * scale;
        __syncthreads();

        // per (g,w): max_k softmax == 1 / sum_k exp(att - max). 48 rows / 8 warps.
        for (int r = 0; r < 6; r++) {
            int row = wid * 6 + r;
            float v0 = sAtt[row * NK + lane];
            float v1 = sAtt[row * NK + 32 + lane];
            float m = fmaxf(v0, v1);
#pragma unroll
            for (int s = 16; s > 0; s >>= 1) m = fmaxf(m, __shfl_xor_sync(0xffffffffu, m, s));
            float e = expf(v0 - m) + expf(v1 - m);
#pragma unroll
            for (int s = 16; s > 0; s >>= 1) e += __shfl_xor_sync(0xffffffffu, e, s);
            if (lane == 0) sRed[row] = 1.f / e;
        }
        __syncthreads();

        // word softmax with query==0 -> -FLT_MAX mask, /5  (warps 0,2,4,6)
        if ((wid & 1) == 0) {
            int gg = wid >> 1;
            float val = -FLT_MAX;
            if (lane < NW) {
                int qi = sQi[gg * NW + lane];
                val = (qi == 0) ? -FLT_MAX : sRed[gg * NW + lane];
            }
            float m = val;
#pragma unroll
            for (int s = 16; s > 0; s >>= 1) m = fmaxf(m, __shfl_xor_sync(0xffffffffu, m, s));
            float e = (lane < NW) ? expf(val - m) : 0.f;
            float ssum = e;
#pragma unroll
            for (int s = 16; s > 0; s >>= 1) ssum += __shfl_xor_sync(0xffffffffu, ssum, s);
            if (lane < NW) sW[gg * NW + lane] = e / ssum * 0.2f;
        }
        __syncthreads();

        // pooling: p[d] = sum_w weight[w] * q_emb[w][d]; K-padded store
        float wl[NW];
#pragma unroll
        for (int w = 0; w < NW; w++) wl[w] = sW[g * NW + w];
        float* pout = &g_P[((size_t)b * NQ + qb + g) * KPAD];
#pragma unroll
        for (int c = 0; c < 5; c++) {
            int d = c * 64 + lg;
            if (d < KPAD) {
                float v = 0.f;
                if (d < EMB) {
#pragma unroll
                    for (int w = 0; w < NW; w++) v += wl[w] * sQ[(g * NW + w) * KSTR + d];
                    pout[d] = v;
                } else {
                    pout[d] = 0.f;
                }
            }
        }
    }
}

// ---------------- launch ------------------------------------------------------
extern "C" void kernel_launch(void* const* d_in, const int* in_sizes, int n_in,
                              void* d_out, int out_size)
{
    const float* wv      = (const float*)d_in[0];
    const float* Wf      = (const float*)d_in[1];
    const float* bf      = (const float*)d_in[2];
    const float* Wp      = (const float*)d_in[3];
    const float* bp      = (const float*)d_in[4];
    const float* Wm      = (const float*)d_in[5];
    const float* bm      = (const float*)d_in[6];
    const float* feature = (const float*)d_in[7];
    const int*   query   = (const int*)d_in[8];
    const int*   label   = (const int*)d_in[9];

    float* outP = (float*)d_out;                               // [256,32,300]
    float* outK = outP + (size_t)BATCH * NQ * EMB;             // [256,64,300]

    void *pP = nullptr, *pWc = nullptr, *pbc = nullptr;
    cudaGetSymbolAddress(&pP,  g_P);
    cudaGetSymbolAddress(&pWc, g_Wc);
    cudaGetSymbolAddress(&pbc, g_bc);

    // 0) combine projection weights: Wc = Wp + 1e-5*Wm, bc = bp + 1e-5*bm
    combine_kernel<<<(NPADB * KPAD + 255) / 256, 256>>>(Wp, bp, Wm, bm);

    // 1) k_emb = feature @ Wf^T + bf + wv[label]   (M=16384, N=300, K=2048)
    {
        dim3 grid((BATCH * NK) / BM, (EMB + BN - 1) / BN);
        gemm_nt_kernel<<<grid, 256>>>(feature, FEAT, Wf, FEAT, EMB, bf,
                                      wv, label, outK, FEAT);
    }

    // 2) attention + pooled p_emb (raw) -> g_P
    {
        int smem = (NK * KSTR + 48 * KSTR + 48 * NK + 48 + 48 + 48) * (int)sizeof(float);
        cudaFuncSetAttribute(attn_kernel, cudaFuncAttributeMaxDynamicSharedMemorySize, smem);
        attn_kernel<<<BATCH, 256, smem>>>(wv, query, outK);
    }

    // 3) p_emb = P @ Wc^T + bc   (M=8192, N=300, K=304)
    {
        dim3 grid((BATCH * NQ) / BM, (EMB + BN - 1) / BN);
        gemm_nt_kernel<<<grid, 256>>>((const float*)pP, KPAD,
                                      (const float*)pWc, KPAD, EMB,
                                      (const float*)pbc, nullptr, nullptr,
                                      outP, KPAD);
    }
}

// round 10
// speedup vs baseline: 1.3352x; 1.3352x over previous
#include <cuda_runtime.h>
#include <cuda_bf16.h>
#include <math.h>
#include <float.h>
#include <stdint.h>

#define VOCAB 30000
#define EMB   300
#define FEAT  2048
#define BATCH 256
#define NQ    32
#define NW    12
#define NK    64

#define KPAD  304
#define NPADB 320

// ---------------- scratch (static device globals; no runtime alloc) ----------
__device__ float g_P[(size_t)BATCH * NQ * KPAD];
__device__ float g_Wc[NPADB * KPAD];
__device__ float g_bc[NPADB];
// Wf packed for mma fragments: word idx = ((c*320 + n)*4 + kb)*8 + w,
// w even -> k-pair w/2, w odd -> k-pair (w-1)/2 + 4 (within the k16 block).
#define BPK_WORDS (32 * 320 * 4 * 8)    // 327680 uint32 = 320 x 2048 bf16
__device__ __align__(16) uint32_t g_Bh[BPK_WORDS];
__device__ __align__(16) uint32_t g_Bl[BPK_WORDS];

// ======================= portable PTX helpers ================================
__device__ __forceinline__ uint32_t smem_u32(const void* p) {
    uint32_t a;
    asm("{ .reg .u64 t; cvta.to.shared.u64 t, %1; cvt.u32.u64 %0, t; }" : "=r"(a) : "l"(p));
    return a;
}
__device__ __forceinline__ void cp16(uint32_t s, const void* g) {
    asm volatile("cp.async.cg.shared.global [%0], [%1], 16;" :: "r"(s), "l"(g) : "memory");
}
__device__ __forceinline__ void mma_bf16(float* c, uint32_t a0, uint32_t a1,
                                         uint32_t a2, uint32_t a3,
                                         uint32_t b0, uint32_t b1) {
    asm volatile(
        "mma.sync.aligned.m16n8k16.row.col.f32.bf16.bf16.f32 "
        "{%0,%1,%2,%3}, {%4,%5,%6,%7}, {%8,%9}, {%0,%1,%2,%3};"
        : "+f"(c[0]), "+f"(c[1]), "+f"(c[2]), "+f"(c[3])
        : "r"(a0), "r"(a1), "r"(a2), "r"(a3), "r"(b0), "r"(b1));
}
__device__ __forceinline__ uint32_t pack_bf2(float x, float y) {
    return (uint32_t)__bfloat16_as_ushort(__float2bfloat16_rn(x)) |
           ((uint32_t)__bfloat16_as_ushort(__float2bfloat16_rn(y)) << 16);
}

// ---------------- kernel: Wf -> split bf16 hi/lo, mma-packed word order ------
__global__ void bconv_kernel(const float* __restrict__ Wf) {
    int idx = blockIdx.x * blockDim.x + threadIdx.x;
    if (idx >= BPK_WORDS) return;
    int w   = idx & 7;
    int kb  = (idx >> 3) & 3;
    int tmp = idx >> 5;
    int n   = tmp % 320;
    int c   = tmp / 320;
    int lp  = (w & 1) ? ((w >> 1) + 4) : (w >> 1);
    int k0  = c * 64 + kb * 16 + lp * 2;
    float x0 = 0.f, x1 = 0.f;
    if (n < EMB) {
        x0 = Wf[(size_t)n * FEAT + k0];
        x1 = Wf[(size_t)n * FEAT + k0 + 1];
    }
    float h0 = __bfloat162float(__float2bfloat16_rn(x0));
    float h1 = __bfloat162float(__float2bfloat16_rn(x1));
    g_Bh[idx] = pack_bf2(x0, x1);
    g_Bl[idx] = pack_bf2(x0 - h0, x1 - h1);
}

// ---------------- kernel: combine projection weights -------------------------
__global__ void combine_kernel(const float* __restrict__ Wp, const float* __restrict__ bp,
                               const float* __restrict__ Wm, const float* __restrict__ bm)
{
    int idx = blockIdx.x * blockDim.x + threadIdx.x;
    if (idx < NPADB * KPAD) {
        int n = idx / KPAD, k = idx % KPAD;
        float v = 0.f;
        if (n < EMB && k < EMB) v = Wp[n * EMB + k] + 1e-5f * Wm[n * EMB + k];
        g_Wc[idx] = v;
    }
    if (idx < NPADB) {
        g_bc[idx] = (idx < EMB) ? (bp[idx] + 1e-5f * bm[idx]) : 0.f;
    }
}

// ============= k_emb GEMM via mma.sync bf16-split (portable HMMA) ============
// C[m,n] = sum_k feature[m,k]*Wf[n,k] + bf[n] + wv[label[m],n]
// Grid (128, 2): BM=128, BN=160 per CTA. 8 warps = 4M x 2N, warp tile 32x80.
// Smem rows: 4 k16-blocks x 32B + 32B pad = 160B (8-bank shift -> conflict-free LDS.64)
#define ROWB 160
#define BNT  160                         // N tile per CTA
#define SM_AH 0
#define SM_AL (SM_AH + 128 * ROWB)       // 20480
#define SM_BH (SM_AL + 128 * ROWB)       // 40960
#define SM_BL (SM_BH + BNT * ROWB)       // 66560
#define SM_GEMM_TOTAL (SM_BL + BNT * ROWB)   // 92160

__global__ __launch_bounds__(256)
void kemb_mma_kernel(const float* __restrict__ feature,
                     const float* __restrict__ bf,
                     const float* __restrict__ wv,
                     const int* __restrict__ label,
                     float* __restrict__ C)
{
    extern __shared__ char smem[];
    const uint32_t sbase = smem_u32(smem);
    const int t    = threadIdx.x;
    const int lane = t & 31;
    const int wid  = t >> 5;
    const int gid  = lane >> 2;        // 0..7
    const int q    = lane & 3;         // 0..3
    const int wm   = (wid & 3) * 32;   // warp M base within tile
    const int wn   = (wid >> 2) * 80;  // warp N base within tile
    const int m0   = blockIdx.x * 128;
    const int ny   = blockIdx.y;       // N half: 0 -> [0,160), 1 -> [160,320)

    const uint2* Ah2 = (const uint2*)(smem + SM_AH);
    const uint2* Al2 = (const uint2*)(smem + SM_AL);
    const uint2* Bh2 = (const uint2*)(smem + SM_BH);
    const uint2* Bl2 = (const uint2*)(smem + SM_BL);

    float acc[2][10][4];
#pragma unroll
    for (int mf = 0; mf < 2; mf++)
#pragma unroll
        for (int f = 0; f < 10; f++)
#pragma unroll
            for (int r = 0; r < 4; r++) acc[mf][f][r] = 0.f;

    for (int c = 0; c < FEAT / 64; c++) {
        __syncthreads();
        // B: cp.async straight copy (pre-packed). 160 rows x 8 x 16B per term.
#pragma unroll
        for (int i = 0; i < 5; i++) {
            int idx = t + i * 256;             // 0..1279
            int n   = idx >> 3;                // local row 0..159
            int sub = idx & 7;
            int kb  = sub >> 1;
            int h   = sub & 1;
            uint32_t soff = (uint32_t)(n * ROWB + kb * 32 + h * 16);
            size_t   goff = ((((size_t)c * 320 + ny * BNT + n) * 4 + kb) * 8 + h * 4);
            cp16(sbase + SM_BH + soff, (const char*)g_Bh + goff * 4);
            cp16(sbase + SM_BL + soff, (const char*)g_Bl + goff * 4);
        }
        asm volatile("cp.async.commit_group;" ::: "memory");

        // A: 128x64 fp32 -> split bf16 hi/lo, packed word order. 4 octets/thread.
#pragma unroll
        for (int i = 0; i < 4; i++) {
            int idx = t + i * 256;             // 0..1023
            int row = idx >> 3;
            int o   = idx & 7;                 // k-octet
            const float4* src = (const float4*)&feature[(size_t)(m0 + row) * FEAT + c * 64 + o * 8];
            float4 v0 = src[0];
            float4 v1 = src[1];
            float fv[8] = {v0.x, v0.y, v0.z, v0.w, v1.x, v1.y, v1.z, v1.w};
            uint32_t* dh = (uint32_t*)(smem + SM_AH) + row * 40 + (o >> 1) * 8 + (o & 1);
            uint32_t* dl = (uint32_t*)(smem + SM_AL) + row * 40 + (o >> 1) * 8 + (o & 1);
#pragma unroll
            for (int j = 0; j < 4; j++) {
                float x0 = fv[2 * j], x1 = fv[2 * j + 1];
                float h0 = __bfloat162float(__float2bfloat16_rn(x0));
                float h1 = __bfloat162float(__float2bfloat16_rn(x1));
                dh[2 * j] = pack_bf2(x0, x1);
                dl[2 * j] = pack_bf2(x0 - h0, x1 - h1);
            }
        }
        asm volatile("cp.async.wait_group 0;" ::: "memory");
        __syncthreads();

        // compute: 4 k16 blocks x 10 n-frags x 2 m-frags x 3 split terms
#pragma unroll
        for (int kb = 0; kb < 4; kb++) {
            uint2 ah[2][2], al[2][2];
#pragma unroll
            for (int mf = 0; mf < 2; mf++) {
                int r0 = wm + mf * 16 + gid;
                ah[mf][0] = Ah2[r0 * 20 + kb * 4 + q];
                ah[mf][1] = Ah2[(r0 + 8) * 20 + kb * 4 + q];
                al[mf][0] = Al2[r0 * 20 + kb * 4 + q];
                al[mf][1] = Al2[(r0 + 8) * 20 + kb * 4 + q];
            }
#pragma unroll
            for (int f = 0; f < 10; f++) {
                int nb = wn + f * 8 + gid;
                uint2 bh = Bh2[nb * 20 + kb * 4 + q];
                uint2 bl = Bl2[nb * 20 + kb * 4 + q];
#pragma unroll
                for (int mf = 0; mf < 2; mf++) {
                    mma_bf16(acc[mf][f], ah[mf][0].x, ah[mf][1].x, ah[mf][0].y, ah[mf][1].y, bh.x, bh.y);
                    mma_bf16(acc[mf][f], al[mf][0].x, al[mf][1].x, al[mf][0].y, al[mf][1].y, bh.x, bh.y);
                    mma_bf16(acc[mf][f], ah[mf][0].x, ah[mf][1].x, ah[mf][0].y, ah[mf][1].y, bl.x, bl.y);
                }
            }
        }
    }

    // epilogue: C[m][n] = acc + bf[n] + wv[label[m]][n]
#pragma unroll
    for (int mf = 0; mf < 2; mf++) {
        int r0 = m0 + wm + mf * 16 + gid;
        int r1 = r0 + 8;
        const float* w0 = wv + (size_t)label[r0] * EMB;
        const float* w1 = wv + (size_t)label[r1] * EMB;
        float* c0p = C + (size_t)r0 * EMB;
        float* c1p = C + (size_t)r1 * EMB;
#pragma unroll
        for (int f = 0; f < 10; f++) {
            int n = ny * BNT + wn + f * 8 + q * 2;
            if (n < EMB) {      // EMB even, pairs fully in/out
                float2 bv = *(const float2*)&bf[n];
                float2 o0, o1;
                o0.x = acc[mf][f][0] + bv.x + w0[n];
                o0.y = acc[mf][f][1] + bv.y + w0[n + 1];
                o1.x = acc[mf][f][2] + bv.x + w1[n];
                o1.y = acc[mf][f][3] + bv.y + w1[n + 1];
                *(float2*)&c0p[n] = o0;
                *(float2*)&c1p[n] = o1;
            }
        }
    }
}

// ---------------- FFMA SGEMM (projection) ------------------------------------
#define BM 128
#define BN 64
#define BKK 16
#define ASTR 132
#define BSTR 68

__global__ __launch_bounds__(256)
void gemm_nt_kernel(const float* __restrict__ A, int lda,
                    const float* __restrict__ Bmat, int ldb, int Nreal,
                    const float* __restrict__ bias,
                    float* __restrict__ C, int K)
{
    __shared__ __align__(16) float As[BKK * ASTR];
    __shared__ __align__(16) float Bs[BKK * BSTR];

    const int t  = threadIdx.x;
    const int tx = t & 15;
    const int ty = t >> 4;
    const int m0 = blockIdx.x * BM;
    const int n0 = blockIdx.y * BN;

    float acc[8][4];
#pragma unroll
    for (int i = 0; i < 8; i++)
#pragma unroll
        for (int j = 0; j < 4; j++) acc[i][j] = 0.f;

    for (int k0 = 0; k0 < K; k0 += BKK) {
#pragma unroll
        for (int i = 0; i < 2; i++) {
            int idx = t + i * 256;
            int row = idx >> 2;
            int kc  = (idx & 3) * 4;
            float4 v = *(const float4*)&A[(size_t)(m0 + row) * lda + k0 + kc];
            As[(kc + 0) * ASTR + row] = v.x;
            As[(kc + 1) * ASTR + row] = v.y;
            As[(kc + 2) * ASTR + row] = v.z;
            As[(kc + 3) * ASTR + row] = v.w;
        }
        {
            int row = t >> 2;
            int kc  = (t & 3) * 4;
            int n   = n0 + row;
            float4 v = make_float4(0.f, 0.f, 0.f, 0.f);
            if (n < Nreal) v = *(const float4*)&Bmat[(size_t)n * ldb + k0 + kc];
            Bs[(kc + 0) * BSTR + row] = v.x;
            Bs[(kc + 1) * BSTR + row] = v.y;
            Bs[(kc + 2) * BSTR + row] = v.z;
            Bs[(kc + 3) * BSTR + row] = v.w;
        }
        __syncthreads();

#pragma unroll
        for (int kk = 0; kk < BKK; kk++) {
            float4 a0 = *(const float4*)&As[kk * ASTR + ty * 8];
            float4 a1 = *(const float4*)&As[kk * ASTR + ty * 8 + 4];
            float4 b0 = *(const float4*)&Bs[kk * BSTR + tx * 4];
            float a[8] = {a0.x, a0.y, a0.z, a0.w, a1.x, a1.y, a1.z, a1.w};
            float b[4] = {b0.x, b0.y, b0.z, b0.w};
#pragma unroll
            for (int i = 0; i < 8; i++)
#pragma unroll
                for (int j = 0; j < 4; j++) acc[i][j] += a[i] * b[j];
        }
        __syncthreads();
    }

#pragma unroll
    for (int i = 0; i < 8; i++) {
        int m = m0 + ty * 8 + i;
#pragma unroll
        for (int j = 0; j < 4; j++) {
            int n = n0 + tx * 4 + j;
            if (n < EMB) C[(size_t)m * EMB + n] = acc[i][j] + bias[n];
        }
    }
}

// ---------------- attention + word-softmax pooling (R3-passing version) ------
#define KSTR 308

__global__ __launch_bounds__(256)
void attn_kernel(const float* __restrict__ wv, const int* __restrict__ query,
                 const float* __restrict__ kemb)
{
    extern __shared__ __align__(16) float sm[];
    float* sK   = sm;
    float* sQ   = sK + NK * KSTR;
    float* sAtt = sQ + 48 * KSTR;
    float* sRed = sAtt + 48 * 64;
    float* sW   = sRed + 48;
    int*   sQi  = (int*)(sW + 48);

    const int b    = blockIdx.x;
    const int t    = threadIdx.x;
    const int g    = t >> 6;
    const int lg   = t & 63;
    const int lane = t & 31;
    const int wid  = t >> 5;

    const float* kb = kemb + (size_t)b * NK * EMB;
    for (int idx = t; idx < NK * EMB; idx += 256)
        sK[(idx / EMB) * KSTR + (idx % EMB)] = kb[idx];

    const float scale = 0.0577350269189626f;

    for (int qb = 0; qb < NQ; qb += 4) {
        __syncthreads();
        if (t < 48) {
            int qq = qb + (t / NW);
            sQi[t] = query[((size_t)b * NQ + qq) * NW + (t % NW)];
        }
        __syncthreads();
        for (int idx = t; idx < 48 * EMB; idx += 256) {
            int row = idx / EMB, col = idx % EMB;
            sQ[row * KSTR + col] = wv[(size_t)sQi[row] * EMB + col];
        }
        __syncthreads();

        float acc[NW];
#pragma unroll
        for (int w = 0; w < NW; w++) acc[w] = 0.f;
        const float* kr = &sK[lg * KSTR];
        const float* qr = &sQ[g * NW * KSTR];
        for (int d = 0; d < EMB; d += 4) {
            float4 kv = *(const float4*)&kr[d];
#pragma unroll
            for (int w = 0; w < NW; w++) {
                float4 qv = *(const float4*)&qr[w * KSTR + d];
                acc[w] += kv.x * qv.x + kv.y * qv.y + kv.z * qv.z + kv.w * qv.w;
            }
        }
#pragma unroll
        for (int w = 0; w < NW; w++) sAtt[(g * NW + w) * NK + lg] = acc[w] * scale;
        __syncthreads();

        for (int r = 0; r < 6; r++) {
            int row = wid * 6 + r;
            float v0 = sAtt[row * NK + lane];
            float v1 = sAtt[row * NK + 32 + lane];
            float m = fmaxf(v0, v1);
#pragma unroll
            for (int s = 16; s > 0; s >>= 1) m = fmaxf(m, __shfl_xor_sync(0xffffffffu, m, s));
            float e = expf(v0 - m) + expf(v1 - m);
#pragma unroll
            for (int s = 16; s > 0; s >>= 1) e += __shfl_xor_sync(0xffffffffu, e, s);
            if (lane == 0) sRed[row] = 1.f / e;
        }
        __syncthreads();

        if ((wid & 1) == 0) {
            int gg = wid >> 1;
            float val = -FLT_MAX;
            if (lane < NW) {
                int qi = sQi[gg * NW + lane];
                val = (qi == 0) ? -FLT_MAX : sRed[gg * NW + lane];
            }
            float m = val;
#pragma unroll
            for (int s = 16; s > 0; s >>= 1) m = fmaxf(m, __shfl_xor_sync(0xffffffffu, m, s));
            float e = (lane < NW) ? expf(val - m) : 0.f;
            float ssum = e;
#pragma unroll
            for (int s = 16; s > 0; s >>= 1) ssum += __shfl_xor_sync(0xffffffffu, ssum, s);
            if (lane < NW) sW[gg * NW + lane] = e / ssum * 0.2f;
        }
        __syncthreads();

        float wl[NW];
#pragma unroll
        for (int w = 0; w < NW; w++) wl[w] = sW[g * NW + w];
        float* pout = &g_P[((size_t)b * NQ + qb + g) * KPAD];
#pragma unroll
        for (int c = 0; c < 5; c++) {
            int d = c * 64 + lg;
            if (d < KPAD) {
                float v = 0.f;
                if (d < EMB) {
#pragma unroll
                    for (int w = 0; w < NW; w++) v += wl[w] * sQ[(g * NW + w) * KSTR + d];
                    pout[d] = v;
                } else {
                    pout[d] = 0.f;
                }
            }
        }
    }
}

// ---------------- launch ------------------------------------------------------
extern "C" void kernel_launch(void* const* d_in, const int* in_sizes, int n_in,
                              void* d_out, int out_size)
{
    const float* wv      = (const float*)d_in[0];
    const float* Wf      = (const float*)d_in[1];
    const float* bf      = (const float*)d_in[2];
    const float* Wp      = (const float*)d_in[3];
    const float* bp      = (const float*)d_in[4];
    const float* Wm      = (const float*)d_in[5];
    const float* bm      = (const float*)d_in[6];
    const float* feature = (const float*)d_in[7];
    const int*   query   = (const int*)d_in[8];
    const int*   label   = (const int*)d_in[9];

    float* outP = (float*)d_out;
    float* outK = outP + (size_t)BATCH * NQ * EMB;

    void *pP = nullptr, *pWc = nullptr, *pbc = nullptr;
    cudaGetSymbolAddress(&pP,  g_P);
    cudaGetSymbolAddress(&pWc, g_Wc);
    cudaGetSymbolAddress(&pbc, g_bc);

    // 0) weight prep
    combine_kernel<<<(NPADB * KPAD + 255) / 256, 256>>>(Wp, bp, Wm, bm);
    bconv_kernel<<<(BPK_WORDS + 255) / 256, 256>>>(Wf);

    // 1) k_emb = feature @ Wf^T + bf + wv[label]  — mma.sync bf16-split
    cudaFuncSetAttribute(kemb_mma_kernel,
                         cudaFuncAttributeMaxDynamicSharedMemorySize, SM_GEMM_TOTAL);
    {
        dim3 grid((BATCH * NK) / 128, 2);
        kemb_mma_kernel<<<grid, 256, SM_GEMM_TOTAL>>>(feature, bf, wv, label, outK);
    }

    // 2) attention + pooled p_emb -> g_P
    {
        int smem = (NK * KSTR + 48 * KSTR + 48 * NK + 48 + 48 + 48) * (int)sizeof(float);
        cudaFuncSetAttribute(attn_kernel, cudaFuncAttributeMaxDynamicSharedMemorySize, smem);
        attn_kernel<<<BATCH, 256, smem>>>(wv, query, outK);
    }

    // 3) p_emb = P @ Wc^T + bc
    {
        dim3 grid((BATCH * NQ) / BM, (EMB + BN - 1) / BN);
        gemm_nt_kernel<<<grid, 256>>>((const float*)pP, KPAD,
                                      (const float*)pWc, KPAD, EMB,
                                      (const float*)pbc, outP, KPAD);
    }
}

// round 11
// speedup vs baseline: 2.2025x; 1.6495x over previous
#include <cuda_runtime.h>
#include <cuda_bf16.h>
#include <math.h>
#include <float.h>
#include <stdint.h>

#define VOCAB 30000
#define EMB   300
#define FEAT  2048
#define BATCH 256
#define NQ    32
#define NW    12
#define NK    64

#define KPAD  304
#define NPADB 320

// ---------------- scratch (static device globals; no runtime alloc) ----------
__device__ float g_P[(size_t)BATCH * NQ * KPAD];
__device__ float g_Wc[NPADB * KPAD];
__device__ float g_bc[NPADB];
// Wf packed for mma fragments: word idx = ((c*320 + n)*4 + kb)*8 + w,
// w even -> k-pair w/2, w odd -> k-pair (w-1)/2 + 4 (within the k16 block).
#define BPK_WORDS (32 * 320 * 4 * 8)    // 327680 uint32 = 320 x 2048 bf16
__device__ __align__(16) uint32_t g_Bh[BPK_WORDS];
__device__ __align__(16) uint32_t g_Bl[BPK_WORDS];

// ======================= portable PTX helpers ================================
__device__ __forceinline__ uint32_t smem_u32(const void* p) {
    uint32_t a;
    asm("{ .reg .u64 t; cvta.to.shared.u64 t, %1; cvt.u32.u64 %0, t; }" : "=r"(a) : "l"(p));
    return a;
}
__device__ __forceinline__ void cp16(uint32_t s, const void* g) {
    asm volatile("cp.async.cg.shared.global [%0], [%1], 16;" :: "r"(s), "l"(g) : "memory");
}
__device__ __forceinline__ void mma_bf16(float* c, uint32_t a0, uint32_t a1,
                                         uint32_t a2, uint32_t a3,
                                         uint32_t b0, uint32_t b1) {
    asm volatile(
        "mma.sync.aligned.m16n8k16.row.col.f32.bf16.bf16.f32 "
        "{%0,%1,%2,%3}, {%4,%5,%6,%7}, {%8,%9}, {%0,%1,%2,%3};"
        : "+f"(c[0]), "+f"(c[1]), "+f"(c[2]), "+f"(c[3])
        : "r"(a0), "r"(a1), "r"(a2), "r"(a3), "r"(b0), "r"(b1));
}
__device__ __forceinline__ uint32_t pack_bf2(float x, float y) {
    return (uint32_t)__bfloat16_as_ushort(__float2bfloat16_rn(x)) |
           ((uint32_t)__bfloat16_as_ushort(__float2bfloat16_rn(y)) << 16);
}
// store one k-octet (8 floats) as split bf16 hi/lo in packed fragment order
__device__ __forceinline__ void store_octet_split(uint32_t* dh, uint32_t* dl,
                                                  float4 v0, float4 v1) {
    float fv[8] = {v0.x, v0.y, v0.z, v0.w, v1.x, v1.y, v1.z, v1.w};
#pragma unroll
    for (int j = 0; j < 4; j++) {
        float x0 = fv[2 * j], x1 = fv[2 * j + 1];
        float h0 = __bfloat162float(__float2bfloat16_rn(x0));
        float h1 = __bfloat162float(__float2bfloat16_rn(x1));
        dh[2 * j] = pack_bf2(x0, x1);
        dl[2 * j] = pack_bf2(x0 - h0, x1 - h1);
    }
}

// ---------------- kernel: Wf -> split bf16 hi/lo, mma-packed word order ------
__global__ void bconv_kernel(const float* __restrict__ Wf) {
    int idx = blockIdx.x * blockDim.x + threadIdx.x;
    if (idx >= BPK_WORDS) return;
    int w   = idx & 7;
    int kb  = (idx >> 3) & 3;
    int tmp = idx >> 5;
    int n   = tmp % 320;
    int c   = tmp / 320;
    int lp  = (w & 1) ? ((w >> 1) + 4) : (w >> 1);
    int k0  = c * 64 + kb * 16 + lp * 2;
    float x0 = 0.f, x1 = 0.f;
    if (n < EMB) {
        x0 = Wf[(size_t)n * FEAT + k0];
        x1 = Wf[(size_t)n * FEAT + k0 + 1];
    }
    float h0 = __bfloat162float(__float2bfloat16_rn(x0));
    float h1 = __bfloat162float(__float2bfloat16_rn(x1));
    g_Bh[idx] = pack_bf2(x0, x1);
    g_Bl[idx] = pack_bf2(x0 - h0, x1 - h1);
}

// ---------------- kernel: combine projection weights -------------------------
__global__ void combine_kernel(const float* __restrict__ Wp, const float* __restrict__ bp,
                               const float* __restrict__ Wm, const float* __restrict__ bm)
{
    int idx = blockIdx.x * blockDim.x + threadIdx.x;
    if (idx < NPADB * KPAD) {
        int n = idx / KPAD, k = idx % KPAD;
        float v = 0.f;
        if (n < EMB && k < EMB) v = Wp[n * EMB + k] + 1e-5f * Wm[n * EMB + k];
        g_Wc[idx] = v;
    }
    if (idx < NPADB) {
        g_bc[idx] = (idx < EMB) ? (bp[idx] + 1e-5f * bm[idx]) : 0.f;
    }
}

// ============= k_emb GEMM via mma.sync bf16-split (R9, passing) ==============
#define ROWB 160
#define BNT  160
#define SM_AH 0
#define SM_AL (SM_AH + 128 * ROWB)
#define SM_BH (SM_AL + 128 * ROWB)
#define SM_BL (SM_BH + BNT * ROWB)
#define SM_GEMM_TOTAL (SM_BL + BNT * ROWB)   // 92160

__global__ __launch_bounds__(256)
void kemb_mma_kernel(const float* __restrict__ feature,
                     const float* __restrict__ bf,
                     const float* __restrict__ wv,
                     const int* __restrict__ label,
                     float* __restrict__ C)
{
    extern __shared__ char smem[];
    const uint32_t sbase = smem_u32(smem);
    const int t    = threadIdx.x;
    const int lane = t & 31;
    const int wid  = t >> 5;
    const int gid  = lane >> 2;
    const int q    = lane & 3;
    const int wm   = (wid & 3) * 32;
    const int wn   = (wid >> 2) * 80;
    const int m0   = blockIdx.x * 128;
    const int ny   = blockIdx.y;

    const uint2* Ah2 = (const uint2*)(smem + SM_AH);
    const uint2* Al2 = (const uint2*)(smem + SM_AL);
    const uint2* Bh2 = (const uint2*)(smem + SM_BH);
    const uint2* Bl2 = (const uint2*)(smem + SM_BL);

    float acc[2][10][4];
#pragma unroll
    for (int mf = 0; mf < 2; mf++)
#pragma unroll
        for (int f = 0; f < 10; f++)
#pragma unroll
            for (int r = 0; r < 4; r++) acc[mf][f][r] = 0.f;

    for (int c = 0; c < FEAT / 64; c++) {
        __syncthreads();
#pragma unroll
        for (int i = 0; i < 5; i++) {
            int idx = t + i * 256;
            int n   = idx >> 3;
            int sub = idx & 7;
            int kb  = sub >> 1;
            int h   = sub & 1;
            uint32_t soff = (uint32_t)(n * ROWB + kb * 32 + h * 16);
            size_t   goff = ((((size_t)c * 320 + ny * BNT + n) * 4 + kb) * 8 + h * 4);
            cp16(sbase + SM_BH + soff, (const char*)g_Bh + goff * 4);
            cp16(sbase + SM_BL + soff, (const char*)g_Bl + goff * 4);
        }
        asm volatile("cp.async.commit_group;" ::: "memory");

#pragma unroll
        for (int i = 0; i < 4; i++) {
            int idx = t + i * 256;
            int row = idx >> 3;
            int o   = idx & 7;
            const float4* src = (const float4*)&feature[(size_t)(m0 + row) * FEAT + c * 64 + o * 8];
            uint32_t* dh = (uint32_t*)(smem + SM_AH) + row * 40 + (o >> 1) * 8 + (o & 1);
            uint32_t* dl = (uint32_t*)(smem + SM_AL) + row * 40 + (o >> 1) * 8 + (o & 1);
            store_octet_split(dh, dl, src[0], src[1]);
        }
        asm volatile("cp.async.wait_group 0;" ::: "memory");
        __syncthreads();

#pragma unroll
        for (int kb = 0; kb < 4; kb++) {
            uint2 ah[2][2], al[2][2];
#pragma unroll
            for (int mf = 0; mf < 2; mf++) {
                int r0 = wm + mf * 16 + gid;
                ah[mf][0] = Ah2[r0 * 20 + kb * 4 + q];
                ah[mf][1] = Ah2[(r0 + 8) * 20 + kb * 4 + q];
                al[mf][0] = Al2[r0 * 20 + kb * 4 + q];
                al[mf][1] = Al2[(r0 + 8) * 20 + kb * 4 + q];
            }
#pragma unroll
            for (int f = 0; f < 10; f++) {
                int nb = wn + f * 8 + gid;
                uint2 bh = Bh2[nb * 20 + kb * 4 + q];
                uint2 bl = Bl2[nb * 20 + kb * 4 + q];
#pragma unroll
                for (int mf = 0; mf < 2; mf++) {
                    mma_bf16(acc[mf][f], ah[mf][0].x, ah[mf][1].x, ah[mf][0].y, ah[mf][1].y, bh.x, bh.y);
                    mma_bf16(acc[mf][f], al[mf][0].x, al[mf][1].x, al[mf][0].y, al[mf][1].y, bh.x, bh.y);
                    mma_bf16(acc[mf][f], ah[mf][0].x, ah[mf][1].x, ah[mf][0].y, ah[mf][1].y, bl.x, bl.y);
                }
            }
        }
    }

#pragma unroll
    for (int mf = 0; mf < 2; mf++) {
        int r0 = m0 + wm + mf * 16 + gid;
        int r1 = r0 + 8;
        const float* w0 = wv + (size_t)label[r0] * EMB;
        const float* w1 = wv + (size_t)label[r1] * EMB;
        float* c0p = C + (size_t)r0 * EMB;
        float* c1p = C + (size_t)r1 * EMB;
#pragma unroll
        for (int f = 0; f < 10; f++) {
            int n = blockIdx.y * BNT + wn + f * 8 + q * 2;
            if (n < EMB) {
                float2 bv = *(const float2*)&bf[n];
                float2 o0, o1;
                o0.x = acc[mf][f][0] + bv.x + w0[n];
                o0.y = acc[mf][f][1] + bv.y + w0[n + 1];
                o1.x = acc[mf][f][2] + bv.x + w1[n];
                o1.y = acc[mf][f][3] + bv.y + w1[n + 1];
                *(float2*)&c0p[n] = o0;
                *(float2*)&c1p[n] = o1;
            }
        }
    }
}

// ============= attention via mma.sync bf16-split =============================
// Per batch: att[384,64] = Q(384x300)·K^T. R[row] = 1/sum_k exp(att*scale - max).
// Then word softmax (mask qi==0, /5) and fp32 pooling -> g_P.
// 384 threads = 12 warps; warp wid owns rows [wid*32, wid*32+32) (2 m-frags), all 64 N.
// K-dim in 5 chunks of 64 (cols >= 300 zero-padded).
#define A_SM_QH 0
#define A_SM_QL (A_SM_QH + 384 * ROWB)    // 61440
#define A_SM_KH (A_SM_QL + 384 * ROWB)    // 122880
#define A_SM_KL (A_SM_KH + 64 * ROWB)     // 133120
#define A_SM_QI (A_SM_KL + 64 * ROWB)     // 143360 (384 ints)
#define A_SM_R  (A_SM_QI + 1536)          // 144896 (384 floats)
#define A_SM_WT (A_SM_R + 1536)           // 146432 (384 floats)
#define A_SM_TOTAL (A_SM_WT + 1536)       // 147968
#define QSTR 68                            // fp32 pooling row stride (floats)

__global__ __launch_bounds__(384)
void attn_mma_kernel(const float* __restrict__ wv, const int* __restrict__ query,
                     const float* __restrict__ kemb)
{
    extern __shared__ char smem[];
    const int b    = blockIdx.x;
    const int t    = threadIdx.x;
    const int lane = t & 31;
    const int wid  = t >> 5;
    const int gid  = lane >> 2;
    const int q    = lane & 3;
    const int wbase = wid * 32;

    int*   sQi = (int*)(smem + A_SM_QI);
    float* sR  = (float*)(smem + A_SM_R);
    float* sWt = (float*)(smem + A_SM_WT);

    // query ids for this batch: [32 q x 12 w] contiguous
    if (t < 384) sQi[t] = query[(size_t)b * NQ * NW + t];
    __syncthreads();

    const uint2* Qh2 = (const uint2*)(smem + A_SM_QH);
    const uint2* Ql2 = (const uint2*)(smem + A_SM_QL);
    const uint2* Kh2 = (const uint2*)(smem + A_SM_KH);
    const uint2* Kl2 = (const uint2*)(smem + A_SM_KL);

    float acc[2][8][4];
#pragma unroll
    for (int mf = 0; mf < 2; mf++)
#pragma unroll
        for (int f = 0; f < 8; f++)
#pragma unroll
            for (int r = 0; r < 4; r++) acc[mf][f][r] = 0.f;

    const float* kbgm = kemb + (size_t)b * NK * EMB;

    for (int c = 0; c < 5; c++) {
        __syncthreads();
        // K chunk: 64 rows x 8 octets
        for (int idx = t; idx < 64 * 8; idx += 384) {
            int row = idx >> 3, o = idx & 7;
            int f0 = c * 16 + 2 * o;               // float4 index in row
            float4 v0 = (f0     < 75) ? *(const float4*)&kbgm[row * EMB + 4 * f0]     : make_float4(0,0,0,0);
            float4 v1 = (f0 + 1 < 75) ? *(const float4*)&kbgm[row * EMB + 4 * f0 + 4] : make_float4(0,0,0,0);
            uint32_t* dh = (uint32_t*)(smem + A_SM_KH) + row * 40 + (o >> 1) * 8 + (o & 1);
            uint32_t* dl = (uint32_t*)(smem + A_SM_KL) + row * 40 + (o >> 1) * 8 + (o & 1);
            store_octet_split(dh, dl, v0, v1);
        }
        // Q chunk: 384 rows x 8 octets, gathered from wv[qi[row]]
        for (int idx = t; idx < 384 * 8; idx += 384) {
            int row = idx >> 3, o = idx & 7;
            const float* src = wv + (size_t)sQi[row] * EMB;
            int f0 = c * 16 + 2 * o;
            float4 v0 = (f0     < 75) ? *(const float4*)&src[4 * f0]     : make_float4(0,0,0,0);
            float4 v1 = (f0 + 1 < 75) ? *(const float4*)&src[4 * f0 + 4] : make_float4(0,0,0,0);
            uint32_t* dh = (uint32_t*)(smem + A_SM_QH) + row * 40 + (o >> 1) * 8 + (o & 1);
            uint32_t* dl = (uint32_t*)(smem + A_SM_QL) + row * 40 + (o >> 1) * 8 + (o & 1);
            store_octet_split(dh, dl, v0, v1);
        }
        __syncthreads();

#pragma unroll
        for (int kb = 0; kb < 4; kb++) {
            uint2 ah[2][2], al[2][2];
#pragma unroll
            for (int mf = 0; mf < 2; mf++) {
                int r0 = wbase + mf * 16 + gid;
                ah[mf][0] = Qh2[r0 * 20 + kb * 4 + q];
                ah[mf][1] = Qh2[(r0 + 8) * 20 + kb * 4 + q];
                al[mf][0] = Ql2[r0 * 20 + kb * 4 + q];
                al[mf][1] = Ql2[(r0 + 8) * 20 + kb * 4 + q];
            }
#pragma unroll
            for (int f = 0; f < 8; f++) {
                int nb = f * 8 + gid;
                uint2 bh = Kh2[nb * 20 + kb * 4 + q];
                uint2 bl = Kl2[nb * 20 + kb * 4 + q];
#pragma unroll
                for (int mf = 0; mf < 2; mf++) {
                    mma_bf16(acc[mf][f], ah[mf][0].x, ah[mf][1].x, ah[mf][0].y, ah[mf][1].y, bh.x, bh.y);
                    mma_bf16(acc[mf][f], al[mf][0].x, al[mf][1].x, al[mf][0].y, al[mf][1].y, bh.x, bh.y);
                    mma_bf16(acc[mf][f], ah[mf][0].x, ah[mf][1].x, ah[mf][0].y, ah[mf][1].y, bl.x, bl.y);
                }
            }
        }
    }

    // R[row] = 1 / sum_n exp(att*scale - max). Row's 64 cols live in this
    // thread's 16 vals x the 4 quad lanes (same gid, q=0..3).
    const float scale = 0.05773502691896258f;   // 1/sqrt(300)
#pragma unroll
    for (int mf = 0; mf < 2; mf++) {
#pragma unroll
        for (int h = 0; h < 2; h++) {
            float vs[16];
            float vmax = -FLT_MAX;
#pragma unroll
            for (int f = 0; f < 8; f++) {
                vs[2 * f]     = acc[mf][f][h * 2]     * scale;
                vs[2 * f + 1] = acc[mf][f][h * 2 + 1] * scale;
                vmax = fmaxf(vmax, fmaxf(vs[2 * f], vs[2 * f + 1]));
            }
            vmax = fmaxf(vmax, __shfl_xor_sync(0xffffffffu, vmax, 1));
            vmax = fmaxf(vmax, __shfl_xor_sync(0xffffffffu, vmax, 2));
            float e = 0.f;
#pragma unroll
            for (int i = 0; i < 16; i++) e += __expf(vs[i] - vmax);
            e += __shfl_xor_sync(0xffffffffu, e, 1);
            e += __shfl_xor_sync(0xffffffffu, e, 2);
            if (q == 0) sR[wbase + mf * 16 + h * 8 + gid] = 1.f / e;
        }
    }
    __syncthreads();

    // word softmax per query (mask qi==0), /5
    if (t < 32) {
        float v[NW];
        float m = -FLT_MAX;
#pragma unroll
        for (int w = 0; w < NW; w++) {
            v[w] = (sQi[t * NW + w] == 0) ? -FLT_MAX : sR[t * NW + w];
            m = fmaxf(m, v[w]);
        }
        float s = 0.f;
#pragma unroll
        for (int w = 0; w < NW; w++) { v[w] = __expf(v[w] - m); s += v[w]; }
        float inv = 0.2f / s;
#pragma unroll
        for (int w = 0; w < NW; w++) sWt[t * NW + w] = v[w] * inv;
    }
    __syncthreads();

    // pooling: fp32 re-gather of q_emb chunk-wise, p[q,d] = sum_w wt*q_emb
    float* sQf = (float*)(smem + A_SM_QH);     // 384 x QSTR floats (aliases Q tiles)
    for (int c = 0; c < 5; c++) {
        __syncthreads();
        for (int idx = t; idx < 384 * 16; idx += 384) {
            int row = idx >> 4, j = idx & 15;
            int f0 = c * 16 + j;
            float4 v = (f0 < 75) ? *(const float4*)&wv[(size_t)sQi[row] * EMB + 4 * f0]
                                 : make_float4(0, 0, 0, 0);
            *(float4*)&sQf[row * QSTR + 4 * j] = v;
        }
        __syncthreads();
        for (int idx = t; idx < 32 * 64; idx += 384) {
            int qq = idx >> 6, d = idx & 63;
            int dg = c * 64 + d;
            if (dg < KPAD) {
                float v = 0.f;
                if (dg < EMB) {
#pragma unroll
                    for (int w = 0; w < NW; w++)
                        v += sWt[qq * NW + w] * sQf[(qq * NW + w) * QSTR + d];
                }
                g_P[((size_t)b * NQ + qq) * KPAD + dg] = v;
            }
        }
    }
}

// ---------------- FFMA SGEMM (projection) ------------------------------------
#define BM 128
#define BN 64
#define BKK 16
#define ASTR 132
#define BSTR 68

__global__ __launch_bounds__(256)
void gemm_nt_kernel(const float* __restrict__ A, int lda,
                    const float* __restrict__ Bmat, int ldb, int Nreal,
                    const float* __restrict__ bias,
                    float* __restrict__ C, int K)
{
    __shared__ __align__(16) float As[BKK * ASTR];
    __shared__ __align__(16) float Bs[BKK * BSTR];

    const int t  = threadIdx.x;
    const int tx = t & 15;
    const int ty = t >> 4;
    const int m0 = blockIdx.x * BM;
    const int n0 = blockIdx.y * BN;

    float acc[8][4];
#pragma unroll
    for (int i = 0; i < 8; i++)
#pragma unroll
        for (int j = 0; j < 4; j++) acc[i][j] = 0.f;

    for (int k0 = 0; k0 < K; k0 += BKK) {
#pragma unroll
        for (int i = 0; i < 2; i++) {
            int idx = t + i * 256;
            int row = idx >> 2;
            int kc  = (idx & 3) * 4;
            float4 v = *(const float4*)&A[(size_t)(m0 + row) * lda + k0 + kc];
            As[(kc + 0) * ASTR + row] = v.x;
            As[(kc + 1) * ASTR + row] = v.y;
            As[(kc + 2) * ASTR + row] = v.z;
            As[(kc + 3) * ASTR + row] = v.w;
        }
        {
            int row = t >> 2;
            int kc  = (t & 3) * 4;
            int n   = n0 + row;
            float4 v = make_float4(0.f, 0.f, 0.f, 0.f);
            if (n < Nreal) v = *(const float4*)&Bmat[(size_t)n * ldb + k0 + kc];
            Bs[(kc + 0) * BSTR + row] = v.x;
            Bs[(kc + 1) * BSTR + row] = v.y;
            Bs[(kc + 2) * BSTR + row] = v.z;
            Bs[(kc + 3) * BSTR + row] = v.w;
        }
        __syncthreads();

#pragma unroll
        for (int kk = 0; kk < BKK; kk++) {
            float4 a0 = *(const float4*)&As[kk * ASTR + ty * 8];
            float4 a1 = *(const float4*)&As[kk * ASTR + ty * 8 + 4];
            float4 b0 = *(const float4*)&Bs[kk * BSTR + tx * 4];
            float a[8] = {a0.x, a0.y, a0.z, a0.w, a1.x, a1.y, a1.z, a1.w};
            float b[4] = {b0.x, b0.y, b0.z, b0.w};
#pragma unroll
            for (int i = 0; i < 8; i++)
#pragma unroll
                for (int j = 0; j < 4; j++) acc[i][j] += a[i] * b[j];
        }
        __syncthreads();
    }

#pragma unroll
    for (int i = 0; i < 8; i++) {
        int m = m0 + ty * 8 + i;
#pragma unroll
        for (int j = 0; j < 4; j++) {
            int n = n0 + tx * 4 + j;
            if (n < EMB) C[(size_t)m * EMB + n] = acc[i][j] + bias[n];
        }
    }
}

// ---------------- launch ------------------------------------------------------
extern "C" void kernel_launch(void* const* d_in, const int* in_sizes, int n_in,
                              void* d_out, int out_size)
{
    const float* wv      = (const float*)d_in[0];
    const float* Wf      = (const float*)d_in[1];
    const float* bf      = (const float*)d_in[2];
    const float* Wp      = (const float*)d_in[3];
    const float* bp      = (const float*)d_in[4];
    const float* Wm      = (const float*)d_in[5];
    const float* bm      = (const float*)d_in[6];
    const float* feature = (const float*)d_in[7];
    const int*   query   = (const int*)d_in[8];
    const int*   label   = (const int*)d_in[9];

    float* outP = (float*)d_out;
    float* outK = outP + (size_t)BATCH * NQ * EMB;

    void *pP = nullptr, *pWc = nullptr, *pbc = nullptr;
    cudaGetSymbolAddress(&pP,  g_P);
    cudaGetSymbolAddress(&pWc, g_Wc);
    cudaGetSymbolAddress(&pbc, g_bc);

    // 0) weight prep
    combine_kernel<<<(NPADB * KPAD + 255) / 256, 256>>>(Wp, bp, Wm, bm);
    bconv_kernel<<<(BPK_WORDS + 255) / 256, 256>>>(Wf);

    // 1) k_emb = feature @ Wf^T + bf + wv[label]  — mma.sync bf16-split
    cudaFuncSetAttribute(kemb_mma_kernel,
                         cudaFuncAttributeMaxDynamicSharedMemorySize, SM_GEMM_TOTAL);
    {
        dim3 grid((BATCH * NK) / 128, 2);
        kemb_mma_kernel<<<grid, 256, SM_GEMM_TOTAL>>>(feature, bf, wv, label, outK);
    }

    // 2) attention + pooling — mma.sync bf16-split
    cudaFuncSetAttribute(attn_mma_kernel,
                         cudaFuncAttributeMaxDynamicSharedMemorySize, A_SM_TOTAL);
    attn_mma_kernel<<<BATCH, 384, A_SM_TOTAL>>>(wv, query, outK);

    // 3) p_emb = P @ Wc^T + bc
    {
        dim3 grid((BATCH * NQ) / BM, (EMB + BN - 1) / BN);
        gemm_nt_kernel<<<grid, 256>>>((const float*)pP, KPAD,
                                      (const float*)pWc, KPAD, EMB,
                                      (const float*)pbc, outP, KPAD);
    }
}

// round 12
// speedup vs baseline: 2.2787x; 1.0346x over previous
#include <cuda_runtime.h>
#include <cuda_bf16.h>
#include <math.h>
#include <float.h>
#include <stdint.h>

#define VOCAB 30000
#define EMB   300
#define FEAT  2048
#define BATCH 256
#define NQ    32
#define NW    12
#define NK    64

#define KPAD  320               // g_P row stride (5 x 64 chunks for proj mma)
#define NPADB 320

// ---------------- scratch (static device globals; no runtime alloc) ----------
__device__ float g_P[(size_t)BATCH * NQ * KPAD];
__device__ float g_bc[NPADB];
// Wf packed: word idx = ((c*320 + n)*4 + kb)*8 + w
#define BPK_WORDS (32 * 320 * 4 * 8)
__device__ __align__(16) uint32_t g_Bh[BPK_WORDS];
__device__ __align__(16) uint32_t g_Bl[BPK_WORDS];
// Wc packed (5 chunks x 320 rows): word idx = ((c*320 + n)*4 + kb)*8 + w
#define WCPK_WORDS (5 * 320 * 4 * 8)
__device__ __align__(16) uint32_t g_Wch[WCPK_WORDS];
__device__ __align__(16) uint32_t g_Wcl[WCPK_WORDS];
// wv pre-packed split-bf16, fragment row order: row n -> 160 words
// word wi in row: c = wi/32, r = wi%32, kb = r/8, w = r%8
#define WV_WORDS ((size_t)VOCAB * 160)
__device__ __align__(16) uint32_t g_wvh[WV_WORDS];
__device__ __align__(16) uint32_t g_wvl[WV_WORDS];

// ======================= portable PTX helpers ================================
__device__ __forceinline__ uint32_t smem_u32(const void* p) {
    uint32_t a;
    asm("{ .reg .u64 t; cvta.to.shared.u64 t, %1; cvt.u32.u64 %0, t; }" : "=r"(a) : "l"(p));
    return a;
}
__device__ __forceinline__ void cp16(uint32_t s, const void* g) {
    asm volatile("cp.async.cg.shared.global [%0], [%1], 16;" :: "r"(s), "l"(g) : "memory");
}
__device__ __forceinline__ void mma_bf16(float* c, uint32_t a0, uint32_t a1,
                                         uint32_t a2, uint32_t a3,
                                         uint32_t b0, uint32_t b1) {
    asm volatile(
        "mma.sync.aligned.m16n8k16.row.col.f32.bf16.bf16.f32 "
        "{%0,%1,%2,%3}, {%4,%5,%6,%7}, {%8,%9}, {%0,%1,%2,%3};"
        : "+f"(c[0]), "+f"(c[1]), "+f"(c[2]), "+f"(c[3])
        : "r"(a0), "r"(a1), "r"(a2), "r"(a3), "r"(b0), "r"(b1));
}
__device__ __forceinline__ uint32_t pack_bf2(float x, float y) {
    return (uint32_t)__bfloat16_as_ushort(__float2bfloat16_rn(x)) |
           ((uint32_t)__bfloat16_as_ushort(__float2bfloat16_rn(y)) << 16);
}
__device__ __forceinline__ void split2(float x0, float x1, uint32_t& h, uint32_t& l) {
    float h0 = __bfloat162float(__float2bfloat16_rn(x0));
    float h1 = __bfloat162float(__float2bfloat16_rn(x1));
    h = pack_bf2(x0, x1);
    l = pack_bf2(x0 - h0, x1 - h1);
}
__device__ __forceinline__ void store_octet_split(uint32_t* dh, uint32_t* dl,
                                                  float4 v0, float4 v1) {
    float fv[8] = {v0.x, v0.y, v0.z, v0.w, v1.x, v1.y, v1.z, v1.w};
#pragma unroll
    for (int j = 0; j < 4; j++) {
        uint32_t h, l;
        split2(fv[2 * j], fv[2 * j + 1], h, l);
        dh[2 * j] = h;
        dl[2 * j] = l;
    }
}

// ---------------- kernel: Wf -> split bf16 hi/lo, mma-packed word order ------
__global__ void bconv_kernel(const float* __restrict__ Wf) {
    int idx = blockIdx.x * blockDim.x + threadIdx.x;
    if (idx >= BPK_WORDS) return;
    int w   = idx & 7;
    int kb  = (idx >> 3) & 3;
    int tmp = idx >> 5;
    int n   = tmp % 320;
    int c   = tmp / 320;
    int lp  = (w & 1) ? ((w >> 1) + 4) : (w >> 1);
    int k0  = c * 64 + kb * 16 + lp * 2;
    float x0 = 0.f, x1 = 0.f;
    if (n < EMB) {
        x0 = Wf[(size_t)n * FEAT + k0];
        x1 = Wf[(size_t)n * FEAT + k0 + 1];
    }
    uint32_t h, l;
    split2(x0, x1, h, l);
    g_Bh[idx] = h;
    g_Bl[idx] = l;
}

// ---------------- kernel: Wc = Wp + 1e-5*Wm -> packed split bf16 -------------
__global__ void combine_kernel(const float* __restrict__ Wp, const float* __restrict__ bp,
                               const float* __restrict__ Wm, const float* __restrict__ bm)
{
    int idx = blockIdx.x * blockDim.x + threadIdx.x;
    if (idx < WCPK_WORDS) {
        int w   = idx & 7;
        int kb  = (idx >> 3) & 3;
        int tmp = idx >> 5;
        int n   = tmp % 320;
        int c   = tmp / 320;
        int lp  = (w & 1) ? ((w >> 1) + 4) : (w >> 1);
        int k0  = c * 64 + kb * 16 + lp * 2;
        float x0 = 0.f, x1 = 0.f;
        if (n < EMB) {
            if (k0 < EMB)     x0 = Wp[n * EMB + k0]     + 1e-5f * Wm[n * EMB + k0];
            if (k0 + 1 < EMB) x1 = Wp[n * EMB + k0 + 1] + 1e-5f * Wm[n * EMB + k0 + 1];
        }
        uint32_t h, l;
        split2(x0, x1, h, l);
        g_Wch[idx] = h;
        g_Wcl[idx] = l;
    }
    if (idx < NPADB) {
        g_bc[idx] = (idx < EMB) ? (bp[idx] + 1e-5f * bm[idx]) : 0.f;
    }
}

// ---------------- kernel: wv -> packed split bf16 rows -----------------------
__global__ void wvpack_kernel(const float* __restrict__ wv) {
    size_t idx = (size_t)blockIdx.x * blockDim.x + threadIdx.x;
    if (idx >= WV_WORDS) return;
    int wi = (int)(idx % 160);
    size_t n = idx / 160;
    int c  = wi >> 5;
    int r  = wi & 31;
    int kb = r >> 3;
    int w  = r & 7;
    int lp = (w & 1) ? ((w >> 1) + 4) : (w >> 1);
    int k0 = c * 64 + kb * 16 + lp * 2;
    float x0 = (k0     < EMB) ? wv[n * EMB + k0]     : 0.f;
    float x1 = (k0 + 1 < EMB) ? wv[n * EMB + k0 + 1] : 0.f;
    uint32_t h, l;
    split2(x0, x1, h, l);
    g_wvh[idx] = h;
    g_wvl[idx] = l;
}

// ============= k_emb GEMM via mma.sync bf16-split (R9/R10, passing) ==========
#define ROWB 160
#define BNT  160
#define SM_AH 0
#define SM_AL (SM_AH + 128 * ROWB)
#define SM_BH (SM_AL + 128 * ROWB)
#define SM_BL (SM_BH + BNT * ROWB)
#define SM_GEMM_TOTAL (SM_BL + BNT * ROWB)   // 92160

__global__ __launch_bounds__(256)
void kemb_mma_kernel(const float* __restrict__ feature,
                     const float* __restrict__ bf,
                     const float* __restrict__ wv,
                     const int* __restrict__ label,
                     float* __restrict__ C)
{
    extern __shared__ char smem[];
    const uint32_t sbase = smem_u32(smem);
    const int t    = threadIdx.x;
    const int lane = t & 31;
    const int wid  = t >> 5;
    const int gid  = lane >> 2;
    const int q    = lane & 3;
    const int wm   = (wid & 3) * 32;
    const int wn   = (wid >> 2) * 80;
    const int m0   = blockIdx.x * 128;
    const int ny   = blockIdx.y;

    const uint2* Ah2 = (const uint2*)(smem + SM_AH);
    const uint2* Al2 = (const uint2*)(smem + SM_AL);
    const uint2* Bh2 = (const uint2*)(smem + SM_BH);
    const uint2* Bl2 = (const uint2*)(smem + SM_BL);

    float acc[2][10][4];
#pragma unroll
    for (int mf = 0; mf < 2; mf++)
#pragma unroll
        for (int f = 0; f < 10; f++)
#pragma unroll
            for (int r = 0; r < 4; r++) acc[mf][f][r] = 0.f;

    for (int c = 0; c < FEAT / 64; c++) {
        __syncthreads();
#pragma unroll
        for (int i = 0; i < 5; i++) {
            int idx = t + i * 256;
            int n   = idx >> 3;
            int sub = idx & 7;
            int kb  = sub >> 1;
            int h   = sub & 1;
            uint32_t soff = (uint32_t)(n * ROWB + kb * 32 + h * 16);
            size_t   goff = ((((size_t)c * 320 + ny * BNT + n) * 4 + kb) * 8 + h * 4);
            cp16(sbase + SM_BH + soff, (const char*)g_Bh + goff * 4);
            cp16(sbase + SM_BL + soff, (const char*)g_Bl + goff * 4);
        }
        asm volatile("cp.async.commit_group;" ::: "memory");

#pragma unroll
        for (int i = 0; i < 4; i++) {
            int idx = t + i * 256;
            int row = idx >> 3;
            int o   = idx & 7;
            const float4* src = (const float4*)&feature[(size_t)(m0 + row) * FEAT + c * 64 + o * 8];
            uint32_t* dh = (uint32_t*)(smem + SM_AH) + row * 40 + (o >> 1) * 8 + (o & 1);
            uint32_t* dl = (uint32_t*)(smem + SM_AL) + row * 40 + (o >> 1) * 8 + (o & 1);
            store_octet_split(dh, dl, src[0], src[1]);
        }
        asm volatile("cp.async.wait_group 0;" ::: "memory");
        __syncthreads();

#pragma unroll
        for (int kb = 0; kb < 4; kb++) {
            uint2 ah[2][2], al[2][2];
#pragma unroll
            for (int mf = 0; mf < 2; mf++) {
                int r0 = wm + mf * 16 + gid;
                ah[mf][0] = Ah2[r0 * 20 + kb * 4 + q];
                ah[mf][1] = Ah2[(r0 + 8) * 20 + kb * 4 + q];
                al[mf][0] = Al2[r0 * 20 + kb * 4 + q];
                al[mf][1] = Al2[(r0 + 8) * 20 + kb * 4 + q];
            }
#pragma unroll
            for (int f = 0; f < 10; f++) {
                int nb = wn + f * 8 + gid;
                uint2 bh = Bh2[nb * 20 + kb * 4 + q];
                uint2 bl = Bl2[nb * 20 + kb * 4 + q];
#pragma unroll
                for (int mf = 0; mf < 2; mf++) {
                    mma_bf16(acc[mf][f], ah[mf][0].x, ah[mf][1].x, ah[mf][0].y, ah[mf][1].y, bh.x, bh.y);
                    mma_bf16(acc[mf][f], al[mf][0].x, al[mf][1].x, al[mf][0].y, al[mf][1].y, bh.x, bh.y);
                    mma_bf16(acc[mf][f], ah[mf][0].x, ah[mf][1].x, ah[mf][0].y, ah[mf][1].y, bl.x, bl.y);
                }
            }
        }
    }

#pragma unroll
    for (int mf = 0; mf < 2; mf++) {
        int r0 = m0 + wm + mf * 16 + gid;
        int r1 = r0 + 8;
        const float* w0 = wv + (size_t)label[r0] * EMB;
        const float* w1 = wv + (size_t)label[r1] * EMB;
        float* c0p = C + (size_t)r0 * EMB;
        float* c1p = C + (size_t)r1 * EMB;
#pragma unroll
        for (int f = 0; f < 10; f++) {
            int n = ny * BNT + wn + f * 8 + q * 2;
            if (n < EMB) {
                float2 bv = *(const float2*)&bf[n];
                float2 o0, o1;
                o0.x = acc[mf][f][0] + bv.x + w0[n];
                o0.y = acc[mf][f][1] + bv.y + w0[n + 1];
                o1.x = acc[mf][f][2] + bv.x + w1[n];
                o1.y = acc[mf][f][3] + bv.y + w1[n + 1];
                *(float2*)&c0p[n] = o0;
                *(float2*)&c1p[n] = o1;
            }
        }
    }
}

// ============= projection GEMM via mma.sync bf16-split =======================
// outP[m,n] = sum_k P[m,k]*Wc[n,k] + bc[n].  M=8192, N=320 (2 halves), K=320.
__global__ __launch_bounds__(256)
void proj_mma_kernel(const float* __restrict__ P,
                     const float* __restrict__ bias,
                     float* __restrict__ C)
{
    extern __shared__ char smem[];
    const uint32_t sbase = smem_u32(smem);
    const int t    = threadIdx.x;
    const int lane = t & 31;
    const int wid  = t >> 5;
    const int gid  = lane >> 2;
    const int q    = lane & 3;
    const int wm   = (wid & 3) * 32;
    const int wn   = (wid >> 2) * 80;
    const int m0   = blockIdx.x * 128;
    const int ny   = blockIdx.y;

    const uint2* Ah2 = (const uint2*)(smem + SM_AH);
    const uint2* Al2 = (const uint2*)(smem + SM_AL);
    const uint2* Bh2 = (const uint2*)(smem + SM_BH);
    const uint2* Bl2 = (const uint2*)(smem + SM_BL);

    float acc[2][10][4];
#pragma unroll
    for (int mf = 0; mf < 2; mf++)
#pragma unroll
        for (int f = 0; f < 10; f++)
#pragma unroll
            for (int r = 0; r < 4; r++) acc[mf][f][r] = 0.f;

    for (int c = 0; c < 5; c++) {
        __syncthreads();
#pragma unroll
        for (int i = 0; i < 5; i++) {
            int idx = t + i * 256;
            int n   = idx >> 3;
            int sub = idx & 7;
            int kb  = sub >> 1;
            int h   = sub & 1;
            uint32_t soff = (uint32_t)(n * ROWB + kb * 32 + h * 16);
            size_t   goff = ((((size_t)c * 320 + ny * BNT + n) * 4 + kb) * 8 + h * 4);
            cp16(sbase + SM_BH + soff, (const char*)g_Wch + goff * 4);
            cp16(sbase + SM_BL + soff, (const char*)g_Wcl + goff * 4);
        }
        asm volatile("cp.async.commit_group;" ::: "memory");

#pragma unroll
        for (int i = 0; i < 4; i++) {
            int idx = t + i * 256;
            int row = idx >> 3;
            int o   = idx & 7;
            const float4* src = (const float4*)&P[(size_t)(m0 + row) * KPAD + c * 64 + o * 8];
            uint32_t* dh = (uint32_t*)(smem + SM_AH) + row * 40 + (o >> 1) * 8 + (o & 1);
            uint32_t* dl = (uint32_t*)(smem + SM_AL) + row * 40 + (o >> 1) * 8 + (o & 1);
            store_octet_split(dh, dl, src[0], src[1]);
        }
        asm volatile("cp.async.wait_group 0;" ::: "memory");
        __syncthreads();

#pragma unroll
        for (int kb = 0; kb < 4; kb++) {
            uint2 ah[2][2], al[2][2];
#pragma unroll
            for (int mf = 0; mf < 2; mf++) {
                int r0 = wm + mf * 16 + gid;
                ah[mf][0] = Ah2[r0 * 20 + kb * 4 + q];
                ah[mf][1] = Ah2[(r0 + 8) * 20 + kb * 4 + q];
                al[mf][0] = Al2[r0 * 20 + kb * 4 + q];
                al[mf][1] = Al2[(r0 + 8) * 20 + kb * 4 + q];
            }
#pragma unroll
            for (int f = 0; f < 10; f++) {
                int nb = wn + f * 8 + gid;
                uint2 bh = Bh2[nb * 20 + kb * 4 + q];
                uint2 bl = Bl2[nb * 20 + kb * 4 + q];
#pragma unroll
                for (int mf = 0; mf < 2; mf++) {
                    mma_bf16(acc[mf][f], ah[mf][0].x, ah[mf][1].x, ah[mf][0].y, ah[mf][1].y, bh.x, bh.y);
                    mma_bf16(acc[mf][f], al[mf][0].x, al[mf][1].x, al[mf][0].y, al[mf][1].y, bh.x, bh.y);
                    mma_bf16(acc[mf][f], ah[mf][0].x, ah[mf][1].x, ah[mf][0].y, ah[mf][1].y, bl.x, bl.y);
                }
            }
        }
    }

#pragma unroll
    for (int mf = 0; mf < 2; mf++) {
        int r0 = m0 + wm + mf * 16 + gid;
        int r1 = r0 + 8;
        float* c0p = C + (size_t)r0 * EMB;
        float* c1p = C + (size_t)r1 * EMB;
#pragma unroll
        for (int f = 0; f < 10; f++) {
            int n = ny * BNT + wn + f * 8 + q * 2;
            if (n < EMB) {
                float2 bv = *(const float2*)&bias[n];
                float2 o0, o1;
                o0.x = acc[mf][f][0] + bv.x;
                o0.y = acc[mf][f][1] + bv.y;
                o1.x = acc[mf][f][2] + bv.x;
                o1.y = acc[mf][f][3] + bv.y;
                *(float2*)&c0p[n] = o0;
                *(float2*)&c1p[n] = o1;
            }
        }
    }
}

// ============= attention via mma.sync; Q from pre-packed wv ==================
#define A_SM_QH 0
#define A_SM_QL (A_SM_QH + 384 * ROWB)    // 61440
#define A_SM_KH (A_SM_QL + 384 * ROWB)    // 122880
#define A_SM_KL (A_SM_KH + 64 * ROWB)     // 133120
#define A_SM_QI (A_SM_KL + 64 * ROWB)     // 143360 (384 ints)
#define A_SM_R  (A_SM_QI + 1536)          // 144896 (384 floats)
#define A_SM_WT (A_SM_R + 1536)           // 146432 (384 floats)
#define A_SM_TOTAL (A_SM_WT + 1536)       // 147968
#define QSTR 68

__global__ __launch_bounds__(384)
void attn_mma_kernel(const float* __restrict__ wv, const int* __restrict__ query,
                     const float* __restrict__ kemb)
{
    extern __shared__ char smem[];
    const uint32_t sbase = smem_u32(smem);
    const int b    = blockIdx.x;
    const int t    = threadIdx.x;
    const int lane = t & 31;
    const int wid  = t >> 5;
    const int gid  = lane >> 2;
    const int q    = lane & 3;
    const int wbase = wid * 32;

    int*   sQi = (int*)(smem + A_SM_QI);
    float* sR  = (float*)(smem + A_SM_R);
    float* sWt = (float*)(smem + A_SM_WT);

    if (t < 384) sQi[t] = query[(size_t)b * NQ * NW + t];
    __syncthreads();

    const uint2* Qh2 = (const uint2*)(smem + A_SM_QH);
    const uint2* Ql2 = (const uint2*)(smem + A_SM_QL);
    const uint2* Kh2 = (const uint2*)(smem + A_SM_KH);
    const uint2* Kl2 = (const uint2*)(smem + A_SM_KL);

    float acc[2][8][4];
#pragma unroll
    for (int mf = 0; mf < 2; mf++)
#pragma unroll
        for (int f = 0; f < 8; f++)
#pragma unroll
            for (int r = 0; r < 4; r++) acc[mf][f][r] = 0.f;

    const float* kbgm = kemb + (size_t)b * NK * EMB;

    for (int c = 0; c < 5; c++) {
        __syncthreads();
        // Q chunk: pre-packed rows, 128 B per row per term via cp.async
#pragma unroll
        for (int i = 0; i < 8; i++) {
            int idx = t + i * 384;               // 0..3071
            int row = idx >> 3, s = idx & 7;
            size_t base = (size_t)sQi[row] * 160 + c * 32 + s * 4;   // word idx
            uint32_t dst = (uint32_t)(row * ROWB + s * 16);
            cp16(sbase + A_SM_QH + dst, (const char*)g_wvh + base * 4);
            cp16(sbase + A_SM_QL + dst, (const char*)g_wvl + base * 4);
        }
        asm volatile("cp.async.commit_group;" ::: "memory");

        // K chunk: 64 rows x 8 octets, fp32 -> split (small)
        for (int idx = t; idx < 64 * 8; idx += 384) {
            int row = idx >> 3, o = idx & 7;
            int f0 = c * 16 + 2 * o;
            float4 v0 = (f0     < 75) ? *(const float4*)&kbgm[row * EMB + 4 * f0]     : make_float4(0,0,0,0);
            float4 v1 = (f0 + 1 < 75) ? *(const float4*)&kbgm[row * EMB + 4 * f0 + 4] : make_float4(0,0,0,0);
            uint32_t* dh = (uint32_t*)(smem + A_SM_KH) + row * 40 + (o >> 1) * 8 + (o & 1);
            uint32_t* dl = (uint32_t*)(smem + A_SM_KL) + row * 40 + (o >> 1) * 8 + (o & 1);
            store_octet_split(dh, dl, v0, v1);
        }
        asm volatile("cp.async.wait_group 0;" ::: "memory");
        __syncthreads();

#pragma unroll
        for (int kb = 0; kb < 4; kb++) {
            uint2 ah[2][2], al[2][2];
#pragma unroll
            for (int mf = 0; mf < 2; mf++) {
                int r0 = wbase + mf * 16 + gid;
                ah[mf][0] = Qh2[r0 * 20 + kb * 4 + q];
                ah[mf][1] = Qh2[(r0 + 8) * 20 + kb * 4 + q];
                al[mf][0] = Ql2[r0 * 20 + kb * 4 + q];
                al[mf][1] = Ql2[(r0 + 8) * 20 + kb * 4 + q];
            }
#pragma unroll
            for (int f = 0; f < 8; f++) {
                int nb = f * 8 + gid;
                uint2 bh = Kh2[nb * 20 + kb * 4 + q];
                uint2 bl = Kl2[nb * 20 + kb * 4 + q];
#pragma unroll
                for (int mf = 0; mf < 2; mf++) {
                    mma_bf16(acc[mf][f], ah[mf][0].x, ah[mf][1].x, ah[mf][0].y, ah[mf][1].y, bh.x, bh.y);
                    mma_bf16(acc[mf][f], al[mf][0].x, al[mf][1].x, al[mf][0].y, al[mf][1].y, bh.x, bh.y);
                    mma_bf16(acc[mf][f], ah[mf][0].x, ah[mf][1].x, ah[mf][0].y, ah[mf][1].y, bl.x, bl.y);
                }
            }
        }
    }

    // R[row] = 1 / sum_n exp(att*scale - max)
    const float scale = 0.05773502691896258f;
#pragma unroll
    for (int mf = 0; mf < 2; mf++) {
#pragma unroll
        for (int h = 0; h < 2; h++) {
            float vs[16];
            float vmax = -FLT_MAX;
#pragma unroll
            for (int f = 0; f < 8; f++) {
                vs[2 * f]     = acc[mf][f][h * 2]     * scale;
                vs[2 * f + 1] = acc[mf][f][h * 2 + 1] * scale;
                vmax = fmaxf(vmax, fmaxf(vs[2 * f], vs[2 * f + 1]));
            }
            vmax = fmaxf(vmax, __shfl_xor_sync(0xffffffffu, vmax, 1));
            vmax = fmaxf(vmax, __shfl_xor_sync(0xffffffffu, vmax, 2));
            float e = 0.f;
#pragma unroll
            for (int i = 0; i < 16; i++) e += __expf(vs[i] - vmax);
            e += __shfl_xor_sync(0xffffffffu, e, 1);
            e += __shfl_xor_sync(0xffffffffu, e, 2);
            if (q == 0) sR[wbase + mf * 16 + h * 8 + gid] = 1.f / e;
        }
    }
    __syncthreads();

    // word softmax per query (mask qi==0), /5
    if (t < 32) {
        float v[NW];
        float m = -FLT_MAX;
#pragma unroll
        for (int w = 0; w < NW; w++) {
            v[w] = (sQi[t * NW + w] == 0) ? -FLT_MAX : sR[t * NW + w];
            m = fmaxf(m, v[w]);
        }
        float s = 0.f;
#pragma unroll
        for (int w = 0; w < NW; w++) { v[w] = __expf(v[w] - m); s += v[w]; }
        float inv = 0.2f / s;
#pragma unroll
        for (int w = 0; w < NW; w++) sWt[t * NW + w] = v[w] * inv;
    }
    __syncthreads();

    // pooling: fp32 re-gather of q_emb chunk-wise (exact)
    float* sQf = (float*)(smem + A_SM_QH);
    for (int c = 0; c < 5; c++) {
        __syncthreads();
        for (int idx = t; idx < 384 * 16; idx += 384) {
            int row = idx >> 4, j = idx & 15;
            int f0 = c * 16 + j;
            float4 v = (f0 < 75) ? *(const float4*)&wv[(size_t)sQi[row] * EMB + 4 * f0]
                                 : make_float4(0, 0, 0, 0);
            *(float4*)&sQf[row * QSTR + 4 * j] = v;
        }
        __syncthreads();
        for (int idx = t; idx < 32 * 64; idx += 384) {
            int qq = idx >> 6, d = idx & 63;
            int dg = c * 64 + d;
            float v = 0.f;
            if (dg < EMB) {
#pragma unroll
                for (int w = 0; w < NW; w++)
                    v += sWt[qq * NW + w] * sQf[(qq * NW + w) * QSTR + d];
            }
            g_P[((size_t)b * NQ + qq) * KPAD + dg] = v;
        }
    }
}

// ---------------- launch ------------------------------------------------------
extern "C" void kernel_launch(void* const* d_in, const int* in_sizes, int n_in,
                              void* d_out, int out_size)
{
    const float* wv      = (const float*)d_in[0];
    const float* Wf      = (const float*)d_in[1];
    const float* bf      = (const float*)d_in[2];
    const float* Wp      = (const float*)d_in[3];
    const float* bp      = (const float*)d_in[4];
    const float* Wm      = (const float*)d_in[5];
    const float* bm      = (const float*)d_in[6];
    const float* feature = (const float*)d_in[7];
    const int*   query   = (const int*)d_in[8];
    const int*   label   = (const int*)d_in[9];

    float* outP = (float*)d_out;
    float* outK = outP + (size_t)BATCH * NQ * EMB;

    void *pP = nullptr, *pbc = nullptr;
    cudaGetSymbolAddress(&pP,  g_P);
    cudaGetSymbolAddress(&pbc, g_bc);

    // 0) weight/wv prep
    combine_kernel<<<(WCPK_WORDS + 255) / 256, 256>>>(Wp, bp, Wm, bm);
    bconv_kernel<<<(BPK_WORDS + 255) / 256, 256>>>(Wf);
    wvpack_kernel<<<(int)((WV_WORDS + 255) / 256), 256>>>(wv);

    // 1) k_emb = feature @ Wf^T + bf + wv[label]
    cudaFuncSetAttribute(kemb_mma_kernel,
                         cudaFuncAttributeMaxDynamicSharedMemorySize, SM_GEMM_TOTAL);
    {
        dim3 grid((BATCH * NK) / 128, 2);
        kemb_mma_kernel<<<grid, 256, SM_GEMM_TOTAL>>>(feature, bf, wv, label, outK);
    }

    // 2) attention + pooling
    cudaFuncSetAttribute(attn_mma_kernel,
                         cudaFuncAttributeMaxDynamicSharedMemorySize, A_SM_TOTAL);
    attn_mma_kernel<<<BATCH, 384, A_SM_TOTAL>>>(wv, query, outK);

    // 3) p_emb = P @ Wc^T + bc
    cudaFuncSetAttribute(proj_mma_kernel,
                         cudaFuncAttributeMaxDynamicSharedMemorySize, SM_GEMM_TOTAL);
    {
        dim3 grid((BATCH * NQ) / 128, 2);
        proj_mma_kernel<<<grid, 256, SM_GEMM_TOTAL>>>((const float*)pP,
                                                      (const float*)pbc, outP);
    }
}

// round 13
// speedup vs baseline: 2.4337x; 1.0680x over previous
#include <cuda_runtime.h>
#include <cuda_bf16.h>
#include <math.h>
#include <float.h>
#include <stdint.h>

#define VOCAB 30000
#define EMB   300
#define FEAT  2048
#define BATCH 256
#define NQ    32
#define NW    12
#define NK    64

#define KPAD  320               // g_P row stride (5 x 64 chunks for proj mma)
#define NPADB 320

// ---------------- scratch (static device globals; no runtime alloc) ----------
__device__ float g_P[(size_t)BATCH * NQ * KPAD];
__device__ float g_bc[NPADB];
// Wf packed: word idx = ((c*320 + n)*4 + kb)*8 + w
#define BPK_WORDS (32 * 320 * 4 * 8)
__device__ __align__(16) uint32_t g_Bh[BPK_WORDS];
__device__ __align__(16) uint32_t g_Bl[BPK_WORDS];
// Wc packed (5 chunks x 320 rows)
#define WCPK_WORDS (5 * 320 * 4 * 8)
__device__ __align__(16) uint32_t g_Wch[WCPK_WORDS];
__device__ __align__(16) uint32_t g_Wcl[WCPK_WORDS];
// wv pre-packed split-bf16 fragment rows: row n -> 160 words
#define WV_WORDS ((size_t)VOCAB * 160)
__device__ __align__(16) uint32_t g_wvh[WV_WORDS];
__device__ __align__(16) uint32_t g_wvl[WV_WORDS];

// ======================= portable PTX helpers ================================
__device__ __forceinline__ uint32_t smem_u32(const void* p) {
    uint32_t a;
    asm("{ .reg .u64 t; cvta.to.shared.u64 t, %1; cvt.u32.u64 %0, t; }" : "=r"(a) : "l"(p));
    return a;
}
__device__ __forceinline__ void cp16(uint32_t s, const void* g) {
    asm volatile("cp.async.cg.shared.global [%0], [%1], 16;" :: "r"(s), "l"(g) : "memory");
}
__device__ __forceinline__ void mma_bf16(float* c, uint32_t a0, uint32_t a1,
                                         uint32_t a2, uint32_t a3,
                                         uint32_t b0, uint32_t b1) {
    asm volatile(
        "mma.sync.aligned.m16n8k16.row.col.f32.bf16.bf16.f32 "
        "{%0,%1,%2,%3}, {%4,%5,%6,%7}, {%8,%9}, {%0,%1,%2,%3};"
        : "+f"(c[0]), "+f"(c[1]), "+f"(c[2]), "+f"(c[3])
        : "r"(a0), "r"(a1), "r"(a2), "r"(a3), "r"(b0), "r"(b1));
}
__device__ __forceinline__ uint32_t pack_bf2(float x, float y) {
    return (uint32_t)__bfloat16_as_ushort(__float2bfloat16_rn(x)) |
           ((uint32_t)__bfloat16_as_ushort(__float2bfloat16_rn(y)) << 16);
}
__device__ __forceinline__ void split2(float x0, float x1, uint32_t& h, uint32_t& l) {
    float h0 = __bfloat162float(__float2bfloat16_rn(x0));
    float h1 = __bfloat162float(__float2bfloat16_rn(x1));
    h = pack_bf2(x0, x1);
    l = pack_bf2(x0 - h0, x1 - h1);
}
__device__ __forceinline__ void store_octet_split(uint32_t* dh, uint32_t* dl,
                                                  float4 v0, float4 v1) {
    float fv[8] = {v0.x, v0.y, v0.z, v0.w, v1.x, v1.y, v1.z, v1.w};
#pragma unroll
    for (int j = 0; j < 4; j++) {
        uint32_t h, l;
        split2(fv[2 * j], fv[2 * j + 1], h, l);
        dh[2 * j] = h;
        dl[2 * j] = l;
    }
}

// ---------------- kernel: Wf -> split bf16 hi/lo, mma-packed word order ------
__global__ void bconv_kernel(const float* __restrict__ Wf) {
    int idx = blockIdx.x * blockDim.x + threadIdx.x;
    if (idx >= BPK_WORDS) return;
    int w   = idx & 7;
    int kb  = (idx >> 3) & 3;
    int tmp = idx >> 5;
    int n   = tmp % 320;
    int c   = tmp / 320;
    int lp  = (w & 1) ? ((w >> 1) + 4) : (w >> 1);
    int k0  = c * 64 + kb * 16 + lp * 2;
    float x0 = 0.f, x1 = 0.f;
    if (n < EMB) {
        x0 = Wf[(size_t)n * FEAT + k0];
        x1 = Wf[(size_t)n * FEAT + k0 + 1];
    }
    uint32_t h, l;
    split2(x0, x1, h, l);
    g_Bh[idx] = h;
    g_Bl[idx] = l;
}

// ---------------- kernel: Wc = Wp + 1e-5*Wm -> packed split bf16 -------------
__global__ void combine_kernel(const float* __restrict__ Wp, const float* __restrict__ bp,
                               const float* __restrict__ Wm, const float* __restrict__ bm)
{
    int idx = blockIdx.x * blockDim.x + threadIdx.x;
    if (idx < WCPK_WORDS) {
        int w   = idx & 7;
        int kb  = (idx >> 3) & 3;
        int tmp = idx >> 5;
        int n   = tmp % 320;
        int c   = tmp / 320;
        int lp  = (w & 1) ? ((w >> 1) + 4) : (w >> 1);
        int k0  = c * 64 + kb * 16 + lp * 2;
        float x0 = 0.f, x1 = 0.f;
        if (n < EMB) {
            if (k0 < EMB)     x0 = Wp[n * EMB + k0]     + 1e-5f * Wm[n * EMB + k0];
            if (k0 + 1 < EMB) x1 = Wp[n * EMB + k0 + 1] + 1e-5f * Wm[n * EMB + k0 + 1];
        }
        uint32_t h, l;
        split2(x0, x1, h, l);
        g_Wch[idx] = h;
        g_Wcl[idx] = l;
    }
    if (idx < NPADB) {
        g_bc[idx] = (idx < EMB) ? (bp[idx] + 1e-5f * bm[idx]) : 0.f;
    }
}

// ---------------- kernel: wv -> packed split bf16 rows -----------------------
__global__ void wvpack_kernel(const float* __restrict__ wv) {
    size_t idx = (size_t)blockIdx.x * blockDim.x + threadIdx.x;
    if (idx >= WV_WORDS) return;
    int wi = (int)(idx % 160);
    size_t n = idx / 160;
    int c  = wi >> 5;
    int r  = wi & 31;
    int kb = r >> 3;
    int w  = r & 7;
    int lp = (w & 1) ? ((w >> 1) + 4) : (w >> 1);
    int k0 = c * 64 + kb * 16 + lp * 2;
    float x0 = (k0     < EMB) ? wv[n * EMB + k0]     : 0.f;
    float x1 = (k0 + 1 < EMB) ? wv[n * EMB + k0 + 1] : 0.f;
    uint32_t h, l;
    split2(x0, x1, h, l);
    g_wvh[idx] = h;
    g_wvl[idx] = l;
}

// ============= k_emb GEMM: pipelined mma.sync bf16-split =====================
// grid (2, 128): x = N half (adjacent bids share M tile -> L2 reuse of feature),
// y = M tile. A prefetched into registers 1 chunk ahead; B cp.async double-buffered.
#define ROWB 160
#define BNT  160
#define SM_AH  0
#define SM_AL  (SM_AH + 128 * ROWB)          // 20480
#define SM_B0H (SM_AL + 128 * ROWB)          // 40960
#define SM_B0L (SM_B0H + BNT * ROWB)         // 66560
#define SM_B1H (SM_B0L + BNT * ROWB)         // 92160
#define SM_B1L (SM_B1H + BNT * ROWB)         // 117760
#define SM_GEMM_TOTAL (SM_B1L + BNT * ROWB)  // 143360

__global__ __launch_bounds__(256)
void kemb_mma_kernel(const float* __restrict__ feature,
                     const float* __restrict__ bf,
                     const float* __restrict__ wv,
                     const int* __restrict__ label,
                     float* __restrict__ C)
{
    extern __shared__ char smem[];
    const uint32_t sbase = smem_u32(smem);
    const int t    = threadIdx.x;
    const int lane = t & 31;
    const int wid  = t >> 5;
    const int gid  = lane >> 2;
    const int q    = lane & 3;
    const int wm   = (wid & 3) * 32;
    const int wn   = (wid >> 2) * 80;
    const int ny   = blockIdx.x;            // N half
    const int m0   = blockIdx.y * 128;      // M tile

    const uint2* Ah2 = (const uint2*)(smem + SM_AH);
    const uint2* Al2 = (const uint2*)(smem + SM_AL);

    float acc[2][10][4];
#pragma unroll
    for (int mf = 0; mf < 2; mf++)
#pragma unroll
        for (int f = 0; f < 10; f++)
#pragma unroll
            for (int r = 0; r < 4; r++) acc[mf][f][r] = 0.f;

    float4 a4[8];                           // A prefetch registers (1 chunk)

#define KEMB_PREFETCH_A(cc) do {                                              \
    _Pragma("unroll")                                                         \
    for (int i = 0; i < 4; i++) {                                             \
        int idx = t + i * 256;                                                \
        int row = idx >> 3, o = idx & 7;                                      \
        const float4* s_ = (const float4*)&feature[(size_t)(m0 + row) * FEAT  \
                                                   + (cc) * 64 + o * 8];      \
        a4[2 * i]     = s_[0];                                                \
        a4[2 * i + 1] = s_[1];                                                \
    } } while (0)

#define KEMB_ISSUE_B(cc, ss) do {                                             \
    uint32_t bh_ = sbase + ((ss) ? SM_B1H : SM_B0H);                          \
    uint32_t bl_ = sbase + ((ss) ? SM_B1L : SM_B0L);                          \
    _Pragma("unroll")                                                         \
    for (int i = 0; i < 5; i++) {                                             \
        int idx = t + i * 256;                                                \
        int n_  = idx >> 3;                                                   \
        int sub = idx & 7;                                                    \
        int kb_ = sub >> 1, h_ = sub & 1;                                     \
        uint32_t soff = (uint32_t)(n_ * ROWB + kb_ * 32 + h_ * 16);           \
        size_t   goff = ((((size_t)(cc) * 320 + ny * BNT + n_) * 4 + kb_) * 8 \
                         + h_ * 4);                                           \
        cp16(bh_ + soff, (const char*)g_Bh + goff * 4);                       \
        cp16(bl_ + soff, (const char*)g_Bl + goff * 4);                       \
    }                                                                         \
    asm volatile("cp.async.commit_group;" ::: "memory");                      \
    } while (0)

    KEMB_PREFETCH_A(0);
    KEMB_ISSUE_B(0, 0);

    for (int c = 0; c < FEAT / 64; c++) {
        const int s = c & 1;
        // convert chunk c's A registers into Ah/Al (prev mma done: trailing sync)
#pragma unroll
        for (int i = 0; i < 4; i++) {
            int idx = t + i * 256;
            int row = idx >> 3, o = idx & 7;
            uint32_t* dh = (uint32_t*)(smem + SM_AH) + row * 40 + (o >> 1) * 8 + (o & 1);
            uint32_t* dl = (uint32_t*)(smem + SM_AL) + row * 40 + (o >> 1) * 8 + (o & 1);
            store_octet_split(dh, dl, a4[2 * i], a4[2 * i + 1]);
        }
        if (c + 1 < FEAT / 64) {
            KEMB_PREFETCH_A(c + 1);          // LDGs drain behind this chunk's mma
            KEMB_ISSUE_B(c + 1, s ^ 1);
            asm volatile("cp.async.wait_group 1;" ::: "memory");   // B[c] arrived
        } else {
            asm volatile("cp.async.wait_group 0;" ::: "memory");
        }
        __syncthreads();

        const uint2* Bh2 = (const uint2*)(smem + (s ? SM_B1H : SM_B0H));
        const uint2* Bl2 = (const uint2*)(smem + (s ? SM_B1L : SM_B0L));
#pragma unroll
        for (int kb = 0; kb < 4; kb++) {
            uint2 ah[2][2], al[2][2];
#pragma unroll
            for (int mf = 0; mf < 2; mf++) {
                int r0 = wm + mf * 16 + gid;
                ah[mf][0] = Ah2[r0 * 20 + kb * 4 + q];
                ah[mf][1] = Ah2[(r0 + 8) * 20 + kb * 4 + q];
                al[mf][0] = Al2[r0 * 20 + kb * 4 + q];
                al[mf][1] = Al2[(r0 + 8) * 20 + kb * 4 + q];
            }
#pragma unroll
            for (int f = 0; f < 10; f++) {
                int nb = wn + f * 8 + gid;
                uint2 bh = Bh2[nb * 20 + kb * 4 + q];
                uint2 bl = Bl2[nb * 20 + kb * 4 + q];
#pragma unroll
                for (int mf = 0; mf < 2; mf++) {
                    mma_bf16(acc[mf][f], ah[mf][0].x, ah[mf][1].x, ah[mf][0].y, ah[mf][1].y, bh.x, bh.y);
                    mma_bf16(acc[mf][f], al[mf][0].x, al[mf][1].x, al[mf][0].y, al[mf][1].y, bh.x, bh.y);
                    mma_bf16(acc[mf][f], ah[mf][0].x, ah[mf][1].x, ah[mf][0].y, ah[mf][1].y, bl.x, bl.y);
                }
            }
        }
        __syncthreads();                     // Ah/Al free for next convert
    }

#pragma unroll
    for (int mf = 0; mf < 2; mf++) {
        int r0 = m0 + wm + mf * 16 + gid;
        int r1 = r0 + 8;
        const float* w0 = wv + (size_t)label[r0] * EMB;
        const float* w1 = wv + (size_t)label[r1] * EMB;
        float* c0p = C + (size_t)r0 * EMB;
        float* c1p = C + (size_t)r1 * EMB;
#pragma unroll
        for (int f = 0; f < 10; f++) {
            int n = ny * BNT + wn + f * 8 + q * 2;
            if (n < EMB) {
                float2 bv = *(const float2*)&bf[n];
                float2 o0, o1;
                o0.x = acc[mf][f][0] + bv.x + w0[n];
                o0.y = acc[mf][f][1] + bv.y + w0[n + 1];
                o1.x = acc[mf][f][2] + bv.x + w1[n];
                o1.y = acc[mf][f][3] + bv.y + w1[n + 1];
                *(float2*)&c0p[n] = o0;
                *(float2*)&c1p[n] = o1;
            }
        }
    }
#undef KEMB_PREFETCH_A
#undef KEMB_ISSUE_B
}

// ============= projection GEMM via mma.sync bf16-split (R11, passing) ========
// grid (2, 64): x = N half (adjacent bids share A tile), y = M tile.
#define PSM_AH 0
#define PSM_AL (PSM_AH + 128 * ROWB)
#define PSM_BH (PSM_AL + 128 * ROWB)
#define PSM_BL (PSM_BH + BNT * ROWB)
#define PSM_TOTAL (PSM_BL + BNT * ROWB)      // 92160

__global__ __launch_bounds__(256)
void proj_mma_kernel(const float* __restrict__ P,
                     const float* __restrict__ bias,
                     float* __restrict__ C)
{
    extern __shared__ char smem[];
    const uint32_t sbase = smem_u32(smem);
    const int t    = threadIdx.x;
    const int lane = t & 31;
    const int wid  = t >> 5;
    const int gid  = lane >> 2;
    const int q    = lane & 3;
    const int wm   = (wid & 3) * 32;
    const int wn   = (wid >> 2) * 80;
    const int ny   = blockIdx.x;
    const int m0   = blockIdx.y * 128;

    const uint2* Ah2 = (const uint2*)(smem + PSM_AH);
    const uint2* Al2 = (const uint2*)(smem + PSM_AL);
    const uint2* Bh2 = (const uint2*)(smem + PSM_BH);
    const uint2* Bl2 = (const uint2*)(smem + PSM_BL);

    float acc[2][10][4];
#pragma unroll
    for (int mf = 0; mf < 2; mf++)
#pragma unroll
        for (int f = 0; f < 10; f++)
#pragma unroll
            for (int r = 0; r < 4; r++) acc[mf][f][r] = 0.f;

    for (int c = 0; c < 5; c++) {
        __syncthreads();
#pragma unroll
        for (int i = 0; i < 5; i++) {
            int idx = t + i * 256;
            int n   = idx >> 3;
            int sub = idx & 7;
            int kb  = sub >> 1;
            int h   = sub & 1;
            uint32_t soff = (uint32_t)(n * ROWB + kb * 32 + h * 16);
            size_t   goff = ((((size_t)c * 320 + ny * BNT + n) * 4 + kb) * 8 + h * 4);
            cp16(sbase + PSM_BH + soff, (const char*)g_Wch + goff * 4);
            cp16(sbase + PSM_BL + soff, (const char*)g_Wcl + goff * 4);
        }
        asm volatile("cp.async.commit_group;" ::: "memory");

#pragma unroll
        for (int i = 0; i < 4; i++) {
            int idx = t + i * 256;
            int row = idx >> 3;
            int o   = idx & 7;
            const float4* src = (const float4*)&P[(size_t)(m0 + row) * KPAD + c * 64 + o * 8];
            uint32_t* dh = (uint32_t*)(smem + PSM_AH) + row * 40 + (o >> 1) * 8 + (o & 1);
            uint32_t* dl = (uint32_t*)(smem + PSM_AL) + row * 40 + (o >> 1) * 8 + (o & 1);
            store_octet_split(dh, dl, src[0], src[1]);
        }
        asm volatile("cp.async.wait_group 0;" ::: "memory");
        __syncthreads();

#pragma unroll
        for (int kb = 0; kb < 4; kb++) {
            uint2 ah[2][2], al[2][2];
#pragma unroll
            for (int mf = 0; mf < 2; mf++) {
                int r0 = wm + mf * 16 + gid;
                ah[mf][0] = Ah2[r0 * 20 + kb * 4 + q];
                ah[mf][1] = Ah2[(r0 + 8) * 20 + kb * 4 + q];
                al[mf][0] = Al2[r0 * 20 + kb * 4 + q];
                al[mf][1] = Al2[(r0 + 8) * 20 + kb * 4 + q];
            }
#pragma unroll
            for (int f = 0; f < 10; f++) {
                int nb = wn + f * 8 + gid;
                uint2 bh = Bh2[nb * 20 + kb * 4 + q];
                uint2 bl = Bl2[nb * 20 + kb * 4 + q];
#pragma unroll
                for (int mf = 0; mf < 2; mf++) {
                    mma_bf16(acc[mf][f], ah[mf][0].x, ah[mf][1].x, ah[mf][0].y, ah[mf][1].y, bh.x, bh.y);
                    mma_bf16(acc[mf][f], al[mf][0].x, al[mf][1].x, al[mf][0].y, al[mf][1].y, bh.x, bh.y);
                    mma_bf16(acc[mf][f], ah[mf][0].x, ah[mf][1].x, ah[mf][0].y, ah[mf][1].y, bl.x, bl.y);
                }
            }
        }
    }

#pragma unroll
    for (int mf = 0; mf < 2; mf++) {
        int r0 = m0 + wm + mf * 16 + gid;
        int r1 = r0 + 8;
        float* c0p = C + (size_t)r0 * EMB;
        float* c1p = C + (size_t)r1 * EMB;
#pragma unroll
        for (int f = 0; f < 10; f++) {
            int n = ny * BNT + wn + f * 8 + q * 2;
            if (n < EMB) {
                float2 bv = *(const float2*)&bias[n];
                float2 o0, o1;
                o0.x = acc[mf][f][0] + bv.x;
                o0.y = acc[mf][f][1] + bv.y;
                o1.x = acc[mf][f][2] + bv.x;
                o1.y = acc[mf][f][3] + bv.y;
                *(float2*)&c0p[n] = o0;
                *(float2*)&c1p[n] = o1;
            }
        }
    }
}

// ============= attention via mma.sync; Q from pre-packed wv (R11, passing) ===
#define A_SM_QH 0
#define A_SM_QL (A_SM_QH + 384 * ROWB)
#define A_SM_KH (A_SM_QL + 384 * ROWB)
#define A_SM_KL (A_SM_KH + 64 * ROWB)
#define A_SM_QI (A_SM_KL + 64 * ROWB)
#define A_SM_R  (A_SM_QI + 1536)
#define A_SM_WT (A_SM_R + 1536)
#define A_SM_TOTAL (A_SM_WT + 1536)          // 147968
#define QSTR 68

__global__ __launch_bounds__(384)
void attn_mma_kernel(const float* __restrict__ wv, const int* __restrict__ query,
                     const float* __restrict__ kemb)
{
    extern __shared__ char smem[];
    const uint32_t sbase = smem_u32(smem);
    const int b    = blockIdx.x;
    const int t    = threadIdx.x;
    const int lane = t & 31;
    const int wid  = t >> 5;
    const int gid  = lane >> 2;
    const int q    = lane & 3;
    const int wbase = wid * 32;

    int*   sQi = (int*)(smem + A_SM_QI);
    float* sR  = (float*)(smem + A_SM_R);
    float* sWt = (float*)(smem + A_SM_WT);

    if (t < 384) sQi[t] = query[(size_t)b * NQ * NW + t];
    __syncthreads();

    const uint2* Qh2 = (const uint2*)(smem + A_SM_QH);
    const uint2* Ql2 = (const uint2*)(smem + A_SM_QL);
    const uint2* Kh2 = (const uint2*)(smem + A_SM_KH);
    const uint2* Kl2 = (const uint2*)(smem + A_SM_KL);

    float acc[2][8][4];
#pragma unroll
    for (int mf = 0; mf < 2; mf++)
#pragma unroll
        for (int f = 0; f < 8; f++)
#pragma unroll
            for (int r = 0; r < 4; r++) acc[mf][f][r] = 0.f;

    const float* kbgm = kemb + (size_t)b * NK * EMB;

    for (int c = 0; c < 5; c++) {
        __syncthreads();
#pragma unroll
        for (int i = 0; i < 8; i++) {
            int idx = t + i * 384;
            int row = idx >> 3, s = idx & 7;
            size_t base = (size_t)sQi[row] * 160 + c * 32 + s * 4;
            uint32_t dst = (uint32_t)(row * ROWB + s * 16);
            cp16(sbase + A_SM_QH + dst, (const char*)g_wvh + base * 4);
            cp16(sbase + A_SM_QL + dst, (const char*)g_wvl + base * 4);
        }
        asm volatile("cp.async.commit_group;" ::: "memory");

        for (int idx = t; idx < 64 * 8; idx += 384) {
            int row = idx >> 3, o = idx & 7;
            int f0 = c * 16 + 2 * o;
            float4 v0 = (f0     < 75) ? *(const float4*)&kbgm[row * EMB + 4 * f0]     : make_float4(0,0,0,0);
            float4 v1 = (f0 + 1 < 75) ? *(const float4*)&kbgm[row * EMB + 4 * f0 + 4] : make_float4(0,0,0,0);
            uint32_t* dh = (uint32_t*)(smem + A_SM_KH) + row * 40 + (o >> 1) * 8 + (o & 1);
            uint32_t* dl = (uint32_t*)(smem + A_SM_KL) + row * 40 + (o >> 1) * 8 + (o & 1);
            store_octet_split(dh, dl, v0, v1);
        }
        asm volatile("cp.async.wait_group 0;" ::: "memory");
        __syncthreads();

#pragma unroll
        for (int kb = 0; kb < 4; kb++) {
            uint2 ah[2][2], al[2][2];
#pragma unroll
            for (int mf = 0; mf < 2; mf++) {
                int r0 = wbase + mf * 16 + gid;
                ah[mf][0] = Qh2[r0 * 20 + kb * 4 + q];
                ah[mf][1] = Qh2[(r0 + 8) * 20 + kb * 4 + q];
                al[mf][0] = Ql2[r0 * 20 + kb * 4 + q];
                al[mf][1] = Ql2[(r0 + 8) * 20 + kb * 4 + q];
            }
#pragma unroll
            for (int f = 0; f < 8; f++) {
                int nb = f * 8 + gid;
                uint2 bh = Kh2[nb * 20 + kb * 4 + q];
                uint2 bl = Kl2[nb * 20 + kb * 4 + q];
#pragma unroll
                for (int mf = 0; mf < 2; mf++) {
                    mma_bf16(acc[mf][f], ah[mf][0].x, ah[mf][1].x, ah[mf][0].y, ah[mf][1].y, bh.x, bh.y);
                    mma_bf16(acc[mf][f], al[mf][0].x, al[mf][1].x, al[mf][0].y, al[mf][1].y, bh.x, bh.y);
                    mma_bf16(acc[mf][f], ah[mf][0].x, ah[mf][1].x, ah[mf][0].y, ah[mf][1].y, bl.x, bl.y);
                }
            }
        }
    }

    const float scale = 0.05773502691896258f;
#pragma unroll
    for (int mf = 0; mf < 2; mf++) {
#pragma unroll
        for (int h = 0; h < 2; h++) {
            float vs[16];
            float vmax = -FLT_MAX;
#pragma unroll
            for (int f = 0; f < 8; f++) {
                vs[2 * f]     = acc[mf][f][h * 2]     * scale;
                vs[2 * f + 1] = acc[mf][f][h * 2 + 1] * scale;
                vmax = fmaxf(vmax, fmaxf(vs[2 * f], vs[2 * f + 1]));
            }
            vmax = fmaxf(vmax, __shfl_xor_sync(0xffffffffu, vmax, 1));
            vmax = fmaxf(vmax, __shfl_xor_sync(0xffffffffu, vmax, 2));
            float e = 0.f;
#pragma unroll
            for (int i = 0; i < 16; i++) e += __expf(vs[i] - vmax);
            e += __shfl_xor_sync(0xffffffffu, e, 1);
            e += __shfl_xor_sync(0xffffffffu, e, 2);
            if (q == 0) sR[wbase + mf * 16 + h * 8 + gid] = 1.f / e;
        }
    }
    __syncthreads();

    if (t < 32) {
        float v[NW];
        float m = -FLT_MAX;
#pragma unroll
        for (int w = 0; w < NW; w++) {
            v[w] = (sQi[t * NW + w] == 0) ? -FLT_MAX : sR[t * NW + w];
            m = fmaxf(m, v[w]);
        }
        float s = 0.f;
#pragma unroll
        for (int w = 0; w < NW; w++) { v[w] = __expf(v[w] - m); s += v[w]; }
        float inv = 0.2f / s;
#pragma unroll
        for (int w = 0; w < NW; w++) sWt[t * NW + w] = v[w] * inv;
    }
    __syncthreads();

    float* sQf = (float*)(smem + A_SM_QH);
    for (int c = 0; c < 5; c++) {
        __syncthreads();
        for (int idx = t; idx < 384 * 16; idx += 384) {
            int row = idx >> 4, j = idx & 15;
            int f0 = c * 16 + j;
            float4 v = (f0 < 75) ? *(const float4*)&wv[(size_t)sQi[row] * EMB + 4 * f0]
                                 : make_float4(0, 0, 0, 0);
            *(float4*)&sQf[row * QSTR + 4 * j] = v;
        }
        __syncthreads();
        for (int idx = t; idx < 32 * 64; idx += 384) {
            int qq = idx >> 6, d = idx & 63;
            int dg = c * 64 + d;
            float v = 0.f;
            if (dg < EMB) {
#pragma unroll
                for (int w = 0; w < NW; w++)
                    v += sWt[qq * NW + w] * sQf[(qq * NW + w) * QSTR + d];
            }
            g_P[((size_t)b * NQ + qq) * KPAD + dg] = v;
        }
    }
}

// ---------------- launch ------------------------------------------------------
extern "C" void kernel_launch(void* const* d_in, const int* in_sizes, int n_in,
                              void* d_out, int out_size)
{
    const float* wv      = (const float*)d_in[0];
    const float* Wf      = (const float*)d_in[1];
    const float* bf      = (const float*)d_in[2];
    const float* Wp      = (const float*)d_in[3];
    const float* bp      = (const float*)d_in[4];
    const float* Wm      = (const float*)d_in[5];
    const float* bm      = (const float*)d_in[6];
    const float* feature = (const float*)d_in[7];
    const int*   query   = (const int*)d_in[8];
    const int*   label   = (const int*)d_in[9];

    float* outP = (float*)d_out;
    float* outK = outP + (size_t)BATCH * NQ * EMB;

    void *pP = nullptr, *pbc = nullptr;
    cudaGetSymbolAddress(&pP,  g_P);
    cudaGetSymbolAddress(&pbc, g_bc);

    // 0) weight/wv prep
    combine_kernel<<<(WCPK_WORDS + 255) / 256, 256>>>(Wp, bp, Wm, bm);
    bconv_kernel<<<(BPK_WORDS + 255) / 256, 256>>>(Wf);
    wvpack_kernel<<<(int)((WV_WORDS + 255) / 256), 256>>>(wv);

    // 1) k_emb = feature @ Wf^T + bf + wv[label]  (pipelined)
    cudaFuncSetAttribute(kemb_mma_kernel,
                         cudaFuncAttributeMaxDynamicSharedMemorySize, SM_GEMM_TOTAL);
    {
        dim3 grid(2, (BATCH * NK) / 128);
        kemb_mma_kernel<<<grid, 256, SM_GEMM_TOTAL>>>(feature, bf, wv, label, outK);
    }

    // 2) attention + pooling
    cudaFuncSetAttribute(attn_mma_kernel,
                         cudaFuncAttributeMaxDynamicSharedMemorySize, A_SM_TOTAL);
    attn_mma_kernel<<<BATCH, 384, A_SM_TOTAL>>>(wv, query, outK);

    // 3) p_emb = P @ Wc^T + bc
    cudaFuncSetAttribute(proj_mma_kernel,
                         cudaFuncAttributeMaxDynamicSharedMemorySize, PSM_TOTAL);
    {
        dim3 grid(2, (BATCH * NQ) / 128);
        proj_mma_kernel<<<grid, 256, PSM_TOTAL>>>((const float*)pP,
                                                  (const float*)pbc, outP);
    }
}